// round 1
// baseline (speedup 1.0000x reference)
#include <cuda_runtime.h>

#define NN 100000
#define DD 128
#define EE 1600000
#define NEG 0.01f
#define EPSV 1e-5f
#define NB_STATS 512

// ---------------- device scratch (no allocations allowed) ----------------
__device__ float g_h[(size_t)NN * DD];    // GEMM output (h1 / h2)
__device__ float g_buf[(size_t)NN * DD];  // aggregation output (out1-prenorm / agg2)
__device__ int   g_cnt[NN];
__device__ int   g_off[NN + 1];
__device__ int   g_wpos[NN];
__device__ int   g_ssrc[EE];              // src ids grouped by dst (CSR)
__device__ float g_dinv[NN];
__device__ float g_part[NB_STATS * 2 * DD];
__device__ float g_scale[DD];
__device__ float g_shift[DD];

// ---------------- graph preprocessing ----------------
__global__ void k_zero() {
    int i = blockIdx.x * blockDim.x + threadIdx.x;
    if (i < NN) g_cnt[i] = 0;
}

__global__ void k_hist(const int* __restrict__ dst) {
    for (int e = blockIdx.x * blockDim.x + threadIdx.x; e < EE; e += gridDim.x * blockDim.x)
        atomicAdd(&g_cnt[dst[e]], 1);
}

// single-block exclusive scan of g_cnt -> g_off, g_wpos; also dinv = rsqrt(deg+1)
__global__ void k_scan() {
    __shared__ int wsum[32];
    __shared__ int carry_s;
    const int tid = threadIdx.x, lane = tid & 31, wid = tid >> 5;
    if (tid == 0) carry_s = 0;
    __syncthreads();
    for (int base = 0; base < NN; base += 1024) {
        int i = base + tid;
        int v = (i < NN) ? g_cnt[i] : 0;
        if (i < NN) g_dinv[i] = rsqrtf((float)v + 1.0f);
        // inclusive warp scan
        int x = v;
        #pragma unroll
        for (int s = 1; s < 32; s <<= 1) {
            int t = __shfl_up_sync(0xFFFFFFFFu, x, s);
            if (lane >= s) x += t;
        }
        if (lane == 31) wsum[wid] = x;
        __syncthreads();
        if (wid == 0) {
            int y = wsum[lane];
            #pragma unroll
            for (int s = 1; s < 32; s <<= 1) {
                int t = __shfl_up_sync(0xFFFFFFFFu, y, s);
                if (lane >= s) y += t;
            }
            wsum[lane] = y;
        }
        __syncthreads();
        int incl = x + (wid > 0 ? wsum[wid - 1] : 0);
        int excl = incl - v + carry_s;
        if (i < NN) { g_off[i] = excl; g_wpos[i] = excl; }
        __syncthreads();                 // everyone has read carry_s
        if (tid == 0) carry_s += wsum[31];
        __syncthreads();
    }
    if (threadIdx.x == 0) g_off[NN] = carry_s;
}

__global__ void k_scatter(const int* __restrict__ src, const int* __restrict__ dst) {
    for (int e = blockIdx.x * blockDim.x + threadIdx.x; e < EE; e += gridDim.x * blockDim.x) {
        int d = dst[e];
        int p = atomicAdd(&g_wpos[d], 1);
        g_ssrc[p] = src[e];
    }
}

// ---------------- GEMM: C[N,128] = A[N,128] @ W[128,128] ----------------
// FUSE: apply y = leakyrelu(a*scale[c]+shift[c]) to A elements on load (BN1+act)
template <bool FUSE>
__global__ __launch_bounds__(256) void k_gemm(const float* __restrict__ A,
                                              const float* __restrict__ W,
                                              float* __restrict__ C) {
    __shared__ float As[8][128];
    __shared__ float Ws[8][128];
    const int tid = threadIdx.x;
    const int bm = blockIdx.x * 128;
    const int ty = tid >> 4;            // 0..15
    const int tx = tid & 15;            // 0..15
    const int arow = tid >> 1;          // 0..127
    const int acol0 = (tid & 1) * 4;    // 0 or 4
    const int wrow = tid >> 5;          // 0..7
    const int wcol = (tid & 31) * 4;    // 0..124

    float acc[8][8];
    #pragma unroll
    for (int i = 0; i < 8; i++)
        #pragma unroll
        for (int j = 0; j < 8; j++) acc[i][j] = 0.0f;

    for (int k = 0; k < DD; k += 8) {
        float4 av = make_float4(0.f, 0.f, 0.f, 0.f);
        int gr = bm + arow;
        if (gr < NN) av = *(const float4*)(A + (size_t)gr * DD + k + acol0);
        if (FUSE) {
            int c = k + acol0;
            float y;
            y = fmaf(av.x, g_scale[c + 0], g_shift[c + 0]); av.x = y > 0.f ? y : NEG * y;
            y = fmaf(av.y, g_scale[c + 1], g_shift[c + 1]); av.y = y > 0.f ? y : NEG * y;
            y = fmaf(av.z, g_scale[c + 2], g_shift[c + 2]); av.z = y > 0.f ? y : NEG * y;
            y = fmaf(av.w, g_scale[c + 3], g_shift[c + 3]); av.w = y > 0.f ? y : NEG * y;
        }
        As[acol0 + 0][arow] = av.x;
        As[acol0 + 1][arow] = av.y;
        As[acol0 + 2][arow] = av.z;
        As[acol0 + 3][arow] = av.w;
        *(float4*)&Ws[wrow][wcol] = *(const float4*)(W + (size_t)(k + wrow) * DD + wcol);
        __syncthreads();
        #pragma unroll
        for (int kk = 0; kk < 8; kk++) {
            float a[8], b[8];
            #pragma unroll
            for (int i = 0; i < 8; i++) a[i] = As[kk][ty * 8 + i];
            #pragma unroll
            for (int j = 0; j < 8; j++) b[j] = Ws[kk][tx * 8 + j];
            #pragma unroll
            for (int i = 0; i < 8; i++)
                #pragma unroll
                for (int j = 0; j < 8; j++) acc[i][j] = fmaf(a[i], b[j], acc[i][j]);
        }
        __syncthreads();
    }
    #pragma unroll
    for (int i = 0; i < 8; i++) {
        int gr = bm + ty * 8 + i;
        if (gr < NN) {
            *(float4*)(C + (size_t)gr * DD + tx * 8) =
                make_float4(acc[i][0], acc[i][1], acc[i][2], acc[i][3]);
            *(float4*)(C + (size_t)gr * DD + tx * 8 + 4) =
                make_float4(acc[i][4], acc[i][5], acc[i][6], acc[i][7]);
        }
    }
}

// ---------------- per-node CSR aggregation (one warp per dst node) --------
// agg[i] = dinv[i] * ( h[i]*dinv[i] + sum_{e in seg(i)} h[src_e]*dinv[src_e] )
__global__ void k_agg(const float* __restrict__ h, float* __restrict__ agg) {
    int warp = (blockIdx.x * blockDim.x + threadIdx.x) >> 5;
    int lane = threadIdx.x & 31;
    if (warp >= NN) return;
    const float4* __restrict__ hp = (const float4*)h;
    float di = g_dinv[warp];
    float4 a = hp[(size_t)warp * 32 + lane];  // self
    float4 acc;
    acc.x = a.x * di; acc.y = a.y * di; acc.z = a.z * di; acc.w = a.w * di;
    int e0 = g_off[warp], e1 = g_off[warp + 1];
    for (int e = e0; e < e1; e++) {
        int s = g_ssrc[e];
        float w = g_dinv[s];
        float4 v = hp[(size_t)s * 32 + lane];
        acc.x = fmaf(w, v.x, acc.x);
        acc.y = fmaf(w, v.y, acc.y);
        acc.z = fmaf(w, v.z, acc.z);
        acc.w = fmaf(w, v.w, acc.w);
    }
    acc.x *= di; acc.y *= di; acc.z *= di; acc.w *= di;
    ((float4*)agg)[(size_t)warp * 32 + lane] = acc;
}

// ---------------- batch norm statistics ----------------
__global__ void k_bnstats(const float* __restrict__ X) {
    int c = threadIdx.x;  // 128 threads, one column each
    float s = 0.f, ss = 0.f;
    for (int r = blockIdx.x; r < NN; r += NB_STATS) {
        float v = X[(size_t)r * DD + c];
        s += v;
        ss = fmaf(v, v, ss);
    }
    g_part[blockIdx.x * (2 * DD) + c] = s;
    g_part[blockIdx.x * (2 * DD) + DD + c] = ss;
}

__global__ void k_bnfinish(const float* __restrict__ gamma, const float* __restrict__ beta) {
    int c = threadIdx.x;
    float s = 0.f, ss = 0.f;
    for (int b = 0; b < NB_STATS; b++) {
        s += g_part[b * (2 * DD) + c];
        ss += g_part[b * (2 * DD) + DD + c];
    }
    float mean = s * (1.0f / NN);
    float var = ss * (1.0f / NN) - mean * mean;
    float r = rsqrtf(var + EPSV);
    float sc = r * gamma[c];
    g_scale[c] = sc;
    g_shift[c] = fmaf(-mean, sc, beta[c]);
}

// ---------------- final: BN2 + residual + leakyrelu ----------------
__global__ void k_final(const float* __restrict__ agg, const float* __restrict__ x,
                        float* __restrict__ out) {
    int i = blockIdx.x * blockDim.x + threadIdx.x;  // float4 index
    if (i >= NN * DD / 4) return;
    int c = (i & 31) * 4;
    float4 v = ((const float4*)agg)[i];
    float4 xr = ((const float4*)x)[i];
    float y;
    y = fmaf(v.x, g_scale[c + 0], g_shift[c + 0]) + xr.x; v.x = y > 0.f ? y : NEG * y;
    y = fmaf(v.y, g_scale[c + 1], g_shift[c + 1]) + xr.y; v.y = y > 0.f ? y : NEG * y;
    y = fmaf(v.z, g_scale[c + 2], g_shift[c + 2]) + xr.z; v.z = y > 0.f ? y : NEG * y;
    y = fmaf(v.w, g_scale[c + 3], g_shift[c + 3]) + xr.w; v.w = y > 0.f ? y : NEG * y;
    ((float4*)out)[i] = v;
}

// ---------------- launch ----------------
extern "C" void kernel_launch(void* const* d_in, const int* in_sizes, int n_in,
                              void* d_out, int out_size) {
    const float* x   = (const float*)d_in[0];
    const int*   ei  = (const int*)d_in[1];
    const int*   src = ei;
    const int*   dst = ei + EE;
    const float* W1  = (const float*)d_in[2];
    // b1 = d_in[3]: cancels inside BatchNorm (added before mean subtraction)
    const float* g1  = (const float*)d_in[4];
    const float* be1 = (const float*)d_in[5];
    const float* W2  = (const float*)d_in[6];
    // b2 = d_in[7]: cancels likewise
    const float* g2  = (const float*)d_in[8];
    const float* be2 = (const float*)d_in[9];
    float* out = (float*)d_out;

    float* p_h = nullptr;
    float* p_buf = nullptr;
    cudaGetSymbolAddress((void**)&p_h, g_h);
    cudaGetSymbolAddress((void**)&p_buf, g_buf);

    // graph preprocessing (CSR grouping by dst) + degrees
    k_zero<<<(NN + 255) / 256, 256>>>();
    k_hist<<<2048, 256>>>(dst);
    k_scan<<<1, 1024>>>();
    k_scatter<<<2048, 256>>>(src, dst);

    // layer 1: h1 = x @ W1 ; agg1 ; BN1 stats (BN1 apply fused into GEMM2 load)
    k_gemm<false><<<(NN + 127) / 128, 256>>>(x, W1, p_h);
    k_agg<<<(NN + 7) / 8, 256>>>(p_h, p_buf);
    k_bnstats<<<NB_STATS, DD>>>(p_buf);
    k_bnfinish<<<1, DD>>>(g1, be1);

    // layer 2: h2 = leakyrelu(BN1(out1)) @ W2 ; agg2 ; BN2 ; residual ; act
    k_gemm<true><<<(NN + 127) / 128, 256>>>(p_buf, W2, p_h);
    k_agg<<<(NN + 7) / 8, 256>>>(p_h, p_buf);
    k_bnstats<<<NB_STATS, DD>>>(p_buf);
    k_bnfinish<<<1, DD>>>(g2, be2);
    k_final<<<(NN * DD / 4 + 255) / 256, 256>>>(p_buf, x, out);
}

// round 3
// speedup vs baseline: 1.5162x; 1.5162x over previous
#include <cuda_runtime.h>
#include <cuda_bf16.h>
#include <stdint.h>

#define NN 100000
#define DD 128
#define EE 1600000
#define NEG 0.01f
#define EPSV 1e-5f
#define NB_STATS 512
#define SCAN_BLK 98   // ceil(100000/1024)

// ---------------- device scratch (no allocations allowed) ----------------
__device__ float g_h[(size_t)NN * DD];    // GEMM output (h1 / h2)
__device__ float g_buf[(size_t)NN * DD];  // aggregation output
__device__ int   g_cnt[NN];
__device__ int   g_off[NN + 1];
__device__ int   g_wpos[NN];
__device__ int   g_bsum[SCAN_BLK];
__device__ int   g_boff[SCAN_BLK];
__device__ int   g_ssrc[EE];              // src ids grouped by dst (CSR)
__device__ float g_sw[EE];                // dinv[src] grouped by dst
__device__ float g_dinv[NN];
__device__ float g_part[NB_STATS * 2 * DD];
__device__ float g_scale[DD];
__device__ float g_shift[DD];
// W pre-split to bf16 hi/lo, stored as per-thread mma-fragment records:
// record (kb,nf) = 32 lanes x 8 bytes; lane word0 = {W[k0][n],W[k0+1][n]},
// word1 = {W[k0+8][n],W[k0+9][n]} with k0 = kb*16 + 2*(lane%4), n = nf*8 + lane/4.
__device__ __align__(16) uint2 g_w1hi[4096];
__device__ __align__(16) uint2 g_w1lo[4096];
__device__ __align__(16) uint2 g_w2hi[4096];
__device__ __align__(16) uint2 g_w2lo[4096];

// ---------------- helpers ----------------
__device__ __forceinline__ uint32_t pack2(__nv_bfloat16 a, __nv_bfloat16 b) {
    __nv_bfloat162 t = __halves2bfloat162(a, b);
    return *(uint32_t*)&t;
}
__device__ __forceinline__ void split2(float x, float y, uint32_t& hi, uint32_t& lo) {
    __nv_bfloat16 hx = __float2bfloat16_rn(x);
    __nv_bfloat16 hy = __float2bfloat16_rn(y);
    float rx = x - __bfloat162float(hx);
    float ry = y - __bfloat162float(hy);
    hi = pack2(hx, hy);
    lo = pack2(__float2bfloat16_rn(rx), __float2bfloat16_rn(ry));
}
__device__ __forceinline__ void mma16816(float4& d, const uint32_t a0, const uint32_t a1,
                                         const uint32_t a2, const uint32_t a3,
                                         const uint32_t b0, const uint32_t b1) {
    asm volatile(
        "mma.sync.aligned.m16n8k16.row.col.f32.bf16.bf16.f32 "
        "{%0,%1,%2,%3}, {%4,%5,%6,%7}, {%8,%9}, {%0,%1,%2,%3};\n"
        : "+f"(d.x), "+f"(d.y), "+f"(d.z), "+f"(d.w)
        : "r"(a0), "r"(a1), "r"(a2), "r"(a3), "r"(b0), "r"(b1));
}

// ---------------- W prep: split fp32 W -> per-thread bf16 frag records ----------
__global__ void k_prepw(const float* __restrict__ W, uint2* __restrict__ bhi,
                        uint2* __restrict__ blo) {
    int i = blockIdx.x * blockDim.x + threadIdx.x;   // 0..4095
    if (i >= 4096) return;
    int lane = i & 31, rec = i >> 5;
    int kb = rec >> 4, nf = rec & 15;
    int g = lane >> 2, tig = lane & 3;
    int k0 = kb * 16 + 2 * tig;
    int n = nf * 8 + g;
    float w00 = W[(k0 + 0) * DD + n];
    float w01 = W[(k0 + 1) * DD + n];
    float w08 = W[(k0 + 8) * DD + n];
    float w09 = W[(k0 + 9) * DD + n];
    uint32_t h0, l0, h1, l1;
    split2(w00, w01, h0, l0);
    split2(w08, w09, h1, l1);
    bhi[i] = make_uint2(h0, h1);
    blo[i] = make_uint2(l0, l1);
}

// ---------------- graph preprocessing ----------------
__global__ void k_zero() {
    int i = blockIdx.x * blockDim.x + threadIdx.x;
    if (i < NN) g_cnt[i] = 0;
}
__global__ void k_hist(const int* __restrict__ dst) {
    int i = blockIdx.x * blockDim.x + threadIdx.x;
    if (i < EE / 4) {
        int4 d = ((const int4*)dst)[i];
        atomicAdd(&g_cnt[d.x], 1);
        atomicAdd(&g_cnt[d.y], 1);
        atomicAdd(&g_cnt[d.z], 1);
        atomicAdd(&g_cnt[d.w], 1);
    }
}
__global__ __launch_bounds__(1024) void k_scan1() {
    __shared__ int wsum[32];
    int tid = threadIdx.x, lane = tid & 31, wid = tid >> 5;
    int i = blockIdx.x * 1024 + tid;
    int v = (i < NN) ? g_cnt[i] : 0;
    if (i < NN) g_dinv[i] = rsqrtf((float)v + 1.0f);
    int x = v;
    #pragma unroll
    for (int s = 1; s < 32; s <<= 1) {
        int t = __shfl_up_sync(0xFFFFFFFFu, x, s);
        if (lane >= s) x += t;
    }
    if (lane == 31) wsum[wid] = x;
    __syncthreads();
    if (wid == 0) {
        int y = wsum[lane];
        #pragma unroll
        for (int s = 1; s < 32; s <<= 1) {
            int t = __shfl_up_sync(0xFFFFFFFFu, y, s);
            if (lane >= s) y += t;
        }
        wsum[lane] = y;
    }
    __syncthreads();
    int incl = x + (wid > 0 ? wsum[wid - 1] : 0);
    if (i < NN) g_off[i] = incl - v;
    if (tid == 1023) g_bsum[blockIdx.x] = incl;
}
__global__ void k_scan2() {
    __shared__ int ws[4];
    int tid = threadIdx.x, lane = tid & 31, wid = tid >> 5;
    int v = (tid < SCAN_BLK) ? g_bsum[tid] : 0;
    int x = v;
    #pragma unroll
    for (int s = 1; s < 32; s <<= 1) {
        int t = __shfl_up_sync(0xFFFFFFFFu, x, s);
        if (lane >= s) x += t;
    }
    if (lane == 31) ws[wid] = x;
    __syncthreads();
    int add = 0;
    for (int w = 0; w < wid; w++) add += ws[w];
    int incl = x + add;
    if (tid < SCAN_BLK) g_boff[tid] = incl - v;
    if (tid == 127) g_off[NN] = incl;
}
__global__ __launch_bounds__(1024) void k_scan3() {
    int i = blockIdx.x * 1024 + threadIdx.x;
    if (i < NN) {
        int o = g_off[i] + g_boff[blockIdx.x];
        g_off[i] = o;
        g_wpos[i] = o;
    }
}
__global__ void k_scatter(const int* __restrict__ src, const int* __restrict__ dst) {
    for (int e = blockIdx.x * blockDim.x + threadIdx.x; e < EE; e += gridDim.x * blockDim.x) {
        int s = src[e];
        int d = dst[e];
        int p = atomicAdd(&g_wpos[d], 1);
        g_ssrc[p] = s;
        g_sw[p] = g_dinv[s];
    }
}

// ---------------- tensor-core GEMM via mma.sync (bf16 3-term split) -------------
// C[N,128] = A[N,128] @ W[128,128];  D = Ahi*Whi + Alo*Whi + Ahi*Wlo (fp32 accum)
// FUSE: A' = leakyrelu(A*scale + shift) applied on load (BN1 + act)
#define SMEMG (65536 + 1024)
template <bool FUSE>
__global__ __launch_bounds__(256, 2) void k_gemm_mma(const float* __restrict__ A,
                                                     const uint2* __restrict__ Bhi,
                                                     const uint2* __restrict__ Blo,
                                                     float* __restrict__ C) {
    extern __shared__ unsigned char sm[];
    uint2* sWhi = (uint2*)sm;                     // 4096 records * 8B = 32KB
    uint2* sWlo = (uint2*)(sm + 32768);           // 32KB
    float* sSc = (float*)(sm + 65536);            // 512B
    float* sSh = (float*)(sm + 66048);            // 512B
    const int tid = threadIdx.x;

    #pragma unroll
    for (int i = 0; i < 16; i++) {
        sWhi[tid + i * 256] = Bhi[tid + i * 256];
        sWlo[tid + i * 256] = Blo[tid + i * 256];
    }
    if (FUSE && tid < 128) {
        sSc[tid] = g_scale[tid];
        sSh[tid] = g_shift[tid];
    }
    __syncthreads();

    const int w = tid >> 5, lane = tid & 31;
    const int g = lane >> 2, tig = lane & 3;
    const int row0 = blockIdx.x * 128 + w * 16 + g;
    const int row8 = row0 + 8;
    const bool ok0 = row0 < NN, ok8 = row8 < NN;

    float4 acc[16];
    #pragma unroll
    for (int nf = 0; nf < 16; nf++) acc[nf] = make_float4(0.f, 0.f, 0.f, 0.f);

    for (int kb = 0; kb < 8; kb++) {
        const int c0 = kb * 16 + tig * 2;
        const int c1 = c0 + 8;
        float2 v00 = ok0 ? *(const float2*)(A + (size_t)row0 * DD + c0) : make_float2(0.f, 0.f);
        float2 v01 = ok0 ? *(const float2*)(A + (size_t)row0 * DD + c1) : make_float2(0.f, 0.f);
        float2 v10 = ok8 ? *(const float2*)(A + (size_t)row8 * DD + c0) : make_float2(0.f, 0.f);
        float2 v11 = ok8 ? *(const float2*)(A + (size_t)row8 * DD + c1) : make_float2(0.f, 0.f);
        if (FUSE) {
            float2 sc0 = *(const float2*)&sSc[c0], sh0 = *(const float2*)&sSh[c0];
            float2 sc1 = *(const float2*)&sSc[c1], sh1 = *(const float2*)&sSh[c1];
            float y;
            y = fmaf(v00.x, sc0.x, sh0.x); v00.x = y > 0.f ? y : NEG * y;
            y = fmaf(v00.y, sc0.y, sh0.y); v00.y = y > 0.f ? y : NEG * y;
            y = fmaf(v01.x, sc1.x, sh1.x); v01.x = y > 0.f ? y : NEG * y;
            y = fmaf(v01.y, sc1.y, sh1.y); v01.y = y > 0.f ? y : NEG * y;
            y = fmaf(v10.x, sc0.x, sh0.x); v10.x = y > 0.f ? y : NEG * y;
            y = fmaf(v10.y, sc0.y, sh0.y); v10.y = y > 0.f ? y : NEG * y;
            y = fmaf(v11.x, sc1.x, sh1.x); v11.x = y > 0.f ? y : NEG * y;
            y = fmaf(v11.y, sc1.y, sh1.y); v11.y = y > 0.f ? y : NEG * y;
        }
        uint32_t ahi[4], alo[4];
        split2(v00.x, v00.y, ahi[0], alo[0]);   // a0: row g,   k c0..c0+1
        split2(v10.x, v10.y, ahi[1], alo[1]);   // a1: row g+8, k c0..c0+1
        split2(v01.x, v01.y, ahi[2], alo[2]);   // a2: row g,   k c1..c1+1
        split2(v11.x, v11.y, ahi[3], alo[3]);   // a3: row g+8, k c1..c1+1

        const uint2* bh = sWhi + (kb * 16) * 32 + lane;
        const uint2* bl = sWlo + (kb * 16) * 32 + lane;
        #pragma unroll
        for (int nf = 0; nf < 16; nf++) {
            uint2 bhv = bh[nf * 32];
            uint2 blv = bl[nf * 32];
            mma16816(acc[nf], ahi[0], ahi[1], ahi[2], ahi[3], bhv.x, bhv.y);
            mma16816(acc[nf], alo[0], alo[1], alo[2], alo[3], bhv.x, bhv.y);
            mma16816(acc[nf], ahi[0], ahi[1], ahi[2], ahi[3], blv.x, blv.y);
        }
    }

    // store: c0,c1 -> (row0, nf*8+tig*2); c2,c3 -> (row8, same cols)
    if (ok0) {
        #pragma unroll
        for (int nf = 0; nf < 16; nf++)
            *(float2*)(C + (size_t)row0 * DD + nf * 8 + tig * 2) = make_float2(acc[nf].x, acc[nf].y);
    }
    if (ok8) {
        #pragma unroll
        for (int nf = 0; nf < 16; nf++)
            *(float2*)(C + (size_t)row8 * DD + nf * 8 + tig * 2) = make_float2(acc[nf].z, acc[nf].w);
    }
}

// ---------------- per-node CSR aggregation (one warp per dst node) --------
__global__ void k_agg(const float* __restrict__ h, float* __restrict__ agg) {
    int warp = (blockIdx.x * blockDim.x + threadIdx.x) >> 5;
    int lane = threadIdx.x & 31;
    if (warp >= NN) return;
    const float4* __restrict__ hp = (const float4*)h;
    float di = g_dinv[warp];
    float4 a = hp[(size_t)warp * 32 + lane];
    float4 acc = make_float4(a.x * di, a.y * di, a.z * di, a.w * di);
    int e0 = g_off[warp], e1 = g_off[warp + 1];
    for (int e = e0; e < e1; e += 4) {
        int i1 = min(e + 1, e1 - 1), i2 = min(e + 2, e1 - 1), i3 = min(e + 3, e1 - 1);
        int s0 = g_ssrc[e], s1 = g_ssrc[i1], s2 = g_ssrc[i2], s3 = g_ssrc[i3];
        float w0 = g_sw[e];
        float w1 = (e + 1 < e1) ? g_sw[i1] : 0.0f;
        float w2 = (e + 2 < e1) ? g_sw[i2] : 0.0f;
        float w3 = (e + 3 < e1) ? g_sw[i3] : 0.0f;
        float4 v0 = hp[(size_t)s0 * 32 + lane];
        float4 v1 = hp[(size_t)s1 * 32 + lane];
        float4 v2 = hp[(size_t)s2 * 32 + lane];
        float4 v3 = hp[(size_t)s3 * 32 + lane];
        acc.x = fmaf(w0, v0.x, fmaf(w1, v1.x, fmaf(w2, v2.x, fmaf(w3, v3.x, acc.x))));
        acc.y = fmaf(w0, v0.y, fmaf(w1, v1.y, fmaf(w2, v2.y, fmaf(w3, v3.y, acc.y))));
        acc.z = fmaf(w0, v0.z, fmaf(w1, v1.z, fmaf(w2, v2.z, fmaf(w3, v3.z, acc.z))));
        acc.w = fmaf(w0, v0.w, fmaf(w1, v1.w, fmaf(w2, v2.w, fmaf(w3, v3.w, acc.w))));
    }
    acc.x *= di; acc.y *= di; acc.z *= di; acc.w *= di;
    ((float4*)agg)[(size_t)warp * 32 + lane] = acc;
}

// ---------------- batch norm statistics ----------------
__global__ __launch_bounds__(128) void k_bnstats(const float* __restrict__ X) {
    __shared__ float red_s[4][DD];
    __shared__ float red_ss[4][DD];
    int tid = threadIdx.x;
    int c4 = tid & 31;
    int q = tid >> 5;
    float4 s = make_float4(0, 0, 0, 0), ss = make_float4(0, 0, 0, 0);
    for (int r = blockIdx.x * 4 + q; r < NN; r += NB_STATS * 4) {
        float4 v = ((const float4*)X)[(size_t)r * 32 + c4];
        s.x += v.x; s.y += v.y; s.z += v.z; s.w += v.w;
        ss.x = fmaf(v.x, v.x, ss.x); ss.y = fmaf(v.y, v.y, ss.y);
        ss.z = fmaf(v.z, v.z, ss.z); ss.w = fmaf(v.w, v.w, ss.w);
    }
    red_s[q][c4 * 4 + 0] = s.x; red_s[q][c4 * 4 + 1] = s.y;
    red_s[q][c4 * 4 + 2] = s.z; red_s[q][c4 * 4 + 3] = s.w;
    red_ss[q][c4 * 4 + 0] = ss.x; red_ss[q][c4 * 4 + 1] = ss.y;
    red_ss[q][c4 * 4 + 2] = ss.z; red_ss[q][c4 * 4 + 3] = ss.w;
    __syncthreads();
    if (q == 0) {
        #pragma unroll
        for (int k = 0; k < 4; k++) {
            int c = c4 * 4 + k;
            float ts = red_s[0][c] + red_s[1][c] + red_s[2][c] + red_s[3][c];
            float tss = red_ss[0][c] + red_ss[1][c] + red_ss[2][c] + red_ss[3][c];
            g_part[blockIdx.x * (2 * DD) + c] = ts;
            g_part[blockIdx.x * (2 * DD) + DD + c] = tss;
        }
    }
}
__global__ void k_bnfinish(const float* __restrict__ gamma, const float* __restrict__ beta) {
    int c = threadIdx.x;
    float s = 0.f, ss = 0.f;
    for (int b = 0; b < NB_STATS; b++) {
        s += g_part[b * (2 * DD) + c];
        ss += g_part[b * (2 * DD) + DD + c];
    }
    float mean = s * (1.0f / NN);
    float var = ss * (1.0f / NN) - mean * mean;
    float r = rsqrtf(var + EPSV);
    float sc = r * gamma[c];
    g_scale[c] = sc;
    g_shift[c] = fmaf(-mean, sc, beta[c]);
}

// ---------------- final: BN2 + residual + leakyrelu ----------------
__global__ void k_final(const float* __restrict__ agg, const float* __restrict__ x,
                        float* __restrict__ out) {
    int i = blockIdx.x * blockDim.x + threadIdx.x;
    if (i >= NN * DD / 4) return;
    int c = (i & 31) * 4;
    float4 v = ((const float4*)agg)[i];
    float4 xr = ((const float4*)x)[i];
    float y;
    y = fmaf(v.x, g_scale[c + 0], g_shift[c + 0]) + xr.x; v.x = y > 0.f ? y : NEG * y;
    y = fmaf(v.y, g_scale[c + 1], g_shift[c + 1]) + xr.y; v.y = y > 0.f ? y : NEG * y;
    y = fmaf(v.z, g_scale[c + 2], g_shift[c + 2]) + xr.z; v.z = y > 0.f ? y : NEG * y;
    y = fmaf(v.w, g_scale[c + 3], g_shift[c + 3]) + xr.w; v.w = y > 0.f ? y : NEG * y;
    ((float4*)out)[i] = v;
}

// ---------------- launch ----------------
extern "C" void kernel_launch(void* const* d_in, const int* in_sizes, int n_in,
                              void* d_out, int out_size) {
    const float* x   = (const float*)d_in[0];
    const int*   ei  = (const int*)d_in[1];
    const int*   src = ei;
    const int*   dst = ei + EE;
    const float* W1  = (const float*)d_in[2];
    // b1 = d_in[3]: cancels inside BatchNorm
    const float* g1  = (const float*)d_in[4];
    const float* be1 = (const float*)d_in[5];
    const float* W2  = (const float*)d_in[6];
    // b2 = d_in[7]: cancels likewise
    const float* g2  = (const float*)d_in[8];
    const float* be2 = (const float*)d_in[9];
    float* out = (float*)d_out;

    float* p_h = nullptr;
    float* p_buf = nullptr;
    uint2 *p_w1hi, *p_w1lo, *p_w2hi, *p_w2lo;
    cudaGetSymbolAddress((void**)&p_h, g_h);
    cudaGetSymbolAddress((void**)&p_buf, g_buf);
    cudaGetSymbolAddress((void**)&p_w1hi, g_w1hi);
    cudaGetSymbolAddress((void**)&p_w1lo, g_w1lo);
    cudaGetSymbolAddress((void**)&p_w2hi, g_w2hi);
    cudaGetSymbolAddress((void**)&p_w2lo, g_w2lo);

    cudaFuncSetAttribute(k_gemm_mma<false>, cudaFuncAttributeMaxDynamicSharedMemorySize, SMEMG);
    cudaFuncSetAttribute(k_gemm_mma<true>, cudaFuncAttributeMaxDynamicSharedMemorySize, SMEMG);

    // weight prep + graph preprocessing
    k_prepw<<<16, 256>>>(W1, p_w1hi, p_w1lo);
    k_prepw<<<16, 256>>>(W2, p_w2hi, p_w2lo);
    k_zero<<<(NN + 255) / 256, 256>>>();
    k_hist<<<(EE / 4 + 255) / 256, 256>>>(dst);
    k_scan1<<<SCAN_BLK, 1024>>>();
    k_scan2<<<1, 128>>>();
    k_scan3<<<SCAN_BLK, 1024>>>();
    k_scatter<<<2048, 256>>>(src, dst);

    // layer 1
    k_gemm_mma<false><<<(NN + 127) / 128, 256, SMEMG>>>(x, p_w1hi, p_w1lo, p_h);
    k_agg<<<(NN + 7) / 8, 256>>>(p_h, p_buf);
    k_bnstats<<<NB_STATS, 128>>>(p_buf);
    k_bnfinish<<<1, DD>>>(g1, be1);

    // layer 2 (BN1+act fused into GEMM2 A-load)
    k_gemm_mma<true><<<(NN + 127) / 128, 256, SMEMG>>>(p_buf, p_w2hi, p_w2lo, p_h);
    k_agg<<<(NN + 7) / 8, 256>>>(p_h, p_buf);
    k_bnstats<<<NB_STATS, 128>>>(p_buf);
    k_bnfinish<<<1, DD>>>(g2, be2);
    k_final<<<(NN * DD / 4 + 255) / 256, 256>>>(p_buf, x, out);
}

// round 4
// speedup vs baseline: 1.6735x; 1.1037x over previous
#include <cuda_runtime.h>
#include <cuda_bf16.h>
#include <cuda_fp16.h>
#include <stdint.h>

#define NN 100000
#define DD 128
#define EE 1600000
#define NEG 0.01f
#define EPSV 1e-5f
#define NB_STATS 512
#define SCAN_BLK 98   // ceil(100000/1024)

// ---------------- device scratch (no allocations allowed) ----------------
__device__ __half g_h[(size_t)NN * DD];   // GEMM output (h1 / h2), fp16
__device__ float g_buf[(size_t)NN * DD];  // aggregation output (fp32)
__device__ int   g_cnt[NN];
__device__ int   g_off[NN + 1];
__device__ int   g_wpos[NN];
__device__ int   g_bsum[SCAN_BLK];
__device__ int   g_boff[SCAN_BLK];
__device__ uint2 g_edge[EE];              // {src, bits(dinv[src])} grouped by dst
__device__ float g_dinv[NN];
__device__ float g_part[NB_STATS * 2 * DD];
__device__ float g_scale[DD];
__device__ float g_shift[DD];
// W pre-split to bf16 hi/lo, stored as per-thread mma-fragment records
__device__ __align__(16) uint2 g_w1hi[4096];
__device__ __align__(16) uint2 g_w1lo[4096];
__device__ __align__(16) uint2 g_w2hi[4096];
__device__ __align__(16) uint2 g_w2lo[4096];

// ---------------- helpers ----------------
__device__ __forceinline__ uint32_t pack2(__nv_bfloat16 a, __nv_bfloat16 b) {
    __nv_bfloat162 t = __halves2bfloat162(a, b);
    return *(uint32_t*)&t;
}
__device__ __forceinline__ void split2(float x, float y, uint32_t& hi, uint32_t& lo) {
    __nv_bfloat16 hx = __float2bfloat16_rn(x);
    __nv_bfloat16 hy = __float2bfloat16_rn(y);
    float rx = x - __bfloat162float(hx);
    float ry = y - __bfloat162float(hy);
    hi = pack2(hx, hy);
    lo = pack2(__float2bfloat16_rn(rx), __float2bfloat16_rn(ry));
}
__device__ __forceinline__ void mma16816(float4& d, const uint32_t a0, const uint32_t a1,
                                         const uint32_t a2, const uint32_t a3,
                                         const uint32_t b0, const uint32_t b1) {
    asm volatile(
        "mma.sync.aligned.m16n8k16.row.col.f32.bf16.bf16.f32 "
        "{%0,%1,%2,%3}, {%4,%5,%6,%7}, {%8,%9}, {%0,%1,%2,%3};\n"
        : "+f"(d.x), "+f"(d.y), "+f"(d.z), "+f"(d.w)
        : "r"(a0), "r"(a1), "r"(a2), "r"(a3), "r"(b0), "r"(b1));
}

// ---------------- W prep: split fp32 W -> per-thread bf16 frag records ----------
__global__ void k_prepw(const float* __restrict__ W, uint2* __restrict__ bhi,
                        uint2* __restrict__ blo) {
    int i = blockIdx.x * blockDim.x + threadIdx.x;   // 0..4095
    if (i >= 4096) return;
    int lane = i & 31, rec = i >> 5;
    int kb = rec >> 4, nf = rec & 15;
    int g = lane >> 2, tig = lane & 3;
    int k0 = kb * 16 + 2 * tig;
    int n = nf * 8 + g;
    float w00 = W[(k0 + 0) * DD + n];
    float w01 = W[(k0 + 1) * DD + n];
    float w08 = W[(k0 + 8) * DD + n];
    float w09 = W[(k0 + 9) * DD + n];
    uint32_t h0, l0, h1, l1;
    split2(w00, w01, h0, l0);
    split2(w08, w09, h1, l1);
    bhi[i] = make_uint2(h0, h1);
    blo[i] = make_uint2(l0, l1);
}

// ---------------- graph preprocessing ----------------
__global__ void k_zero() {
    int i = blockIdx.x * blockDim.x + threadIdx.x;
    if (i < NN) g_cnt[i] = 0;
}
__global__ void k_hist(const int* __restrict__ dst) {
    int i = blockIdx.x * blockDim.x + threadIdx.x;
    if (i < EE / 4) {
        int4 d = ((const int4*)dst)[i];
        atomicAdd(&g_cnt[d.x], 1);
        atomicAdd(&g_cnt[d.y], 1);
        atomicAdd(&g_cnt[d.z], 1);
        atomicAdd(&g_cnt[d.w], 1);
    }
}
__global__ __launch_bounds__(1024) void k_scan1() {
    __shared__ int wsum[32];
    int tid = threadIdx.x, lane = tid & 31, wid = tid >> 5;
    int i = blockIdx.x * 1024 + tid;
    int v = (i < NN) ? g_cnt[i] : 0;
    if (i < NN) g_dinv[i] = rsqrtf((float)v + 1.0f);
    int x = v;
    #pragma unroll
    for (int s = 1; s < 32; s <<= 1) {
        int t = __shfl_up_sync(0xFFFFFFFFu, x, s);
        if (lane >= s) x += t;
    }
    if (lane == 31) wsum[wid] = x;
    __syncthreads();
    if (wid == 0) {
        int y = wsum[lane];
        #pragma unroll
        for (int s = 1; s < 32; s <<= 1) {
            int t = __shfl_up_sync(0xFFFFFFFFu, y, s);
            if (lane >= s) y += t;
        }
        wsum[lane] = y;
    }
    __syncthreads();
    int incl = x + (wid > 0 ? wsum[wid - 1] : 0);
    if (i < NN) g_off[i] = incl - v;
    if (tid == 1023) g_bsum[blockIdx.x] = incl;
}
__global__ void k_scan2() {
    __shared__ int ws[4];
    int tid = threadIdx.x, lane = tid & 31, wid = tid >> 5;
    int v = (tid < SCAN_BLK) ? g_bsum[tid] : 0;
    int x = v;
    #pragma unroll
    for (int s = 1; s < 32; s <<= 1) {
        int t = __shfl_up_sync(0xFFFFFFFFu, x, s);
        if (lane >= s) x += t;
    }
    if (lane == 31) ws[wid] = x;
    __syncthreads();
    int add = 0;
    for (int w = 0; w < wid; w++) add += ws[w];
    int incl = x + add;
    if (tid < SCAN_BLK) g_boff[tid] = incl - v;
    if (tid == 127) g_off[NN] = incl;
}
__global__ __launch_bounds__(1024) void k_scan3() {
    int i = blockIdx.x * 1024 + threadIdx.x;
    if (i < NN) {
        int o = g_off[i] + g_boff[blockIdx.x];
        g_off[i] = o;
        g_wpos[i] = o;
    }
}
__global__ void k_scatter(const int* __restrict__ src, const int* __restrict__ dst) {
    for (int e = blockIdx.x * blockDim.x + threadIdx.x; e < EE; e += gridDim.x * blockDim.x) {
        int s = src[e];
        int d = dst[e];
        int p = atomicAdd(&g_wpos[d], 1);
        g_edge[p] = make_uint2((uint32_t)s, __float_as_uint(g_dinv[s]));
    }
}

// ---------------- tensor-core GEMM via mma.sync (bf16 3-term split) -------------
// C[N,128](fp16) = A[N,128](fp32) @ W[128,128]
// FUSE: A' = leakyrelu(A*scale + shift) applied on load (BN1 + act)
#define SMEMG (65536 + 1024)
template <bool FUSE>
__global__ __launch_bounds__(256, 2) void k_gemm_mma(const float* __restrict__ A,
                                                     const uint2* __restrict__ Bhi,
                                                     const uint2* __restrict__ Blo,
                                                     __half* __restrict__ C) {
    extern __shared__ unsigned char sm[];
    uint2* sWhi = (uint2*)sm;                     // 32KB
    uint2* sWlo = (uint2*)(sm + 32768);           // 32KB
    float* sSc = (float*)(sm + 65536);
    float* sSh = (float*)(sm + 66048);
    const int tid = threadIdx.x;

    #pragma unroll
    for (int i = 0; i < 16; i++) {
        sWhi[tid + i * 256] = Bhi[tid + i * 256];
        sWlo[tid + i * 256] = Blo[tid + i * 256];
    }
    if (FUSE && tid < 128) {
        sSc[tid] = g_scale[tid];
        sSh[tid] = g_shift[tid];
    }
    __syncthreads();

    const int w = tid >> 5, lane = tid & 31;
    const int g = lane >> 2, tig = lane & 3;
    const int row0 = blockIdx.x * 128 + w * 16 + g;
    const int row8 = row0 + 8;
    const bool ok0 = row0 < NN, ok8 = row8 < NN;

    float4 acc[16];
    #pragma unroll
    for (int nf = 0; nf < 16; nf++) acc[nf] = make_float4(0.f, 0.f, 0.f, 0.f);

    for (int kb = 0; kb < 8; kb++) {
        const int c0 = kb * 16 + tig * 2;
        const int c1 = c0 + 8;
        float2 v00 = ok0 ? *(const float2*)(A + (size_t)row0 * DD + c0) : make_float2(0.f, 0.f);
        float2 v01 = ok0 ? *(const float2*)(A + (size_t)row0 * DD + c1) : make_float2(0.f, 0.f);
        float2 v10 = ok8 ? *(const float2*)(A + (size_t)row8 * DD + c0) : make_float2(0.f, 0.f);
        float2 v11 = ok8 ? *(const float2*)(A + (size_t)row8 * DD + c1) : make_float2(0.f, 0.f);
        if (FUSE) {
            float2 sc0 = *(const float2*)&sSc[c0], sh0 = *(const float2*)&sSh[c0];
            float2 sc1 = *(const float2*)&sSc[c1], sh1 = *(const float2*)&sSh[c1];
            float y;
            y = fmaf(v00.x, sc0.x, sh0.x); v00.x = y > 0.f ? y : NEG * y;
            y = fmaf(v00.y, sc0.y, sh0.y); v00.y = y > 0.f ? y : NEG * y;
            y = fmaf(v01.x, sc1.x, sh1.x); v01.x = y > 0.f ? y : NEG * y;
            y = fmaf(v01.y, sc1.y, sh1.y); v01.y = y > 0.f ? y : NEG * y;
            y = fmaf(v10.x, sc0.x, sh0.x); v10.x = y > 0.f ? y : NEG * y;
            y = fmaf(v10.y, sc0.y, sh0.y); v10.y = y > 0.f ? y : NEG * y;
            y = fmaf(v11.x, sc1.x, sh1.x); v11.x = y > 0.f ? y : NEG * y;
            y = fmaf(v11.y, sc1.y, sh1.y); v11.y = y > 0.f ? y : NEG * y;
        }
        uint32_t ahi[4], alo[4];
        split2(v00.x, v00.y, ahi[0], alo[0]);
        split2(v10.x, v10.y, ahi[1], alo[1]);
        split2(v01.x, v01.y, ahi[2], alo[2]);
        split2(v11.x, v11.y, ahi[3], alo[3]);

        const uint2* bh = sWhi + (kb * 16) * 32 + lane;
        const uint2* bl = sWlo + (kb * 16) * 32 + lane;
        #pragma unroll
        for (int nf = 0; nf < 16; nf++) {
            uint2 bhv = bh[nf * 32];
            uint2 blv = bl[nf * 32];
            mma16816(acc[nf], ahi[0], ahi[1], ahi[2], ahi[3], bhv.x, bhv.y);
            mma16816(acc[nf], alo[0], alo[1], alo[2], alo[3], bhv.x, bhv.y);
            mma16816(acc[nf], ahi[0], ahi[1], ahi[2], ahi[3], blv.x, blv.y);
        }
    }

    if (ok0) {
        #pragma unroll
        for (int nf = 0; nf < 16; nf++) {
            __half2 o = __floats2half2_rn(acc[nf].x, acc[nf].y);
            *(__half2*)(C + (size_t)row0 * DD + nf * 8 + tig * 2) = o;
        }
    }
    if (ok8) {
        #pragma unroll
        for (int nf = 0; nf < 16; nf++) {
            __half2 o = __floats2half2_rn(acc[nf].z, acc[nf].w);
            *(__half2*)(C + (size_t)row8 * DD + nf * 8 + tig * 2) = o;
        }
    }
}

// ---------------- per-node CSR aggregation (one warp per dst node) --------
// fp16 gathers, fp32 accumulate
__global__ void k_agg(const __half* __restrict__ h, float* __restrict__ agg) {
    int warp = (blockIdx.x * blockDim.x + threadIdx.x) >> 5;
    int lane = threadIdx.x & 31;
    if (warp >= NN) return;
    const uint2* __restrict__ hp = (const uint2*)h;   // 4 halves per lane
    float di = g_dinv[warp];
    uint2 sv = hp[(size_t)warp * 32 + lane];
    float2 a01 = __half22float2(*(__half2*)&sv.x);
    float2 a23 = __half22float2(*(__half2*)&sv.y);
    float4 acc = make_float4(a01.x * di, a01.y * di, a23.x * di, a23.y * di);
    int e0 = g_off[warp], e1 = g_off[warp + 1];
    for (int e = e0; e < e1; e += 4) {
        int i1 = min(e + 1, e1 - 1), i2 = min(e + 2, e1 - 1), i3 = min(e + 3, e1 - 1);
        uint2 r0 = g_edge[e], r1 = g_edge[i1], r2 = g_edge[i2], r3 = g_edge[i3];
        float w0 = __uint_as_float(r0.y);
        float w1 = (e + 1 < e1) ? __uint_as_float(r1.y) : 0.0f;
        float w2 = (e + 2 < e1) ? __uint_as_float(r2.y) : 0.0f;
        float w3 = (e + 3 < e1) ? __uint_as_float(r3.y) : 0.0f;
        uint2 v0 = hp[(size_t)r0.x * 32 + lane];
        uint2 v1 = hp[(size_t)r1.x * 32 + lane];
        uint2 v2 = hp[(size_t)r2.x * 32 + lane];
        uint2 v3 = hp[(size_t)r3.x * 32 + lane];
        float2 f;
        f = __half22float2(*(__half2*)&v0.x); acc.x = fmaf(w0, f.x, acc.x); acc.y = fmaf(w0, f.y, acc.y);
        f = __half22float2(*(__half2*)&v0.y); acc.z = fmaf(w0, f.x, acc.z); acc.w = fmaf(w0, f.y, acc.w);
        f = __half22float2(*(__half2*)&v1.x); acc.x = fmaf(w1, f.x, acc.x); acc.y = fmaf(w1, f.y, acc.y);
        f = __half22float2(*(__half2*)&v1.y); acc.z = fmaf(w1, f.x, acc.z); acc.w = fmaf(w1, f.y, acc.w);
        f = __half22float2(*(__half2*)&v2.x); acc.x = fmaf(w2, f.x, acc.x); acc.y = fmaf(w2, f.y, acc.y);
        f = __half22float2(*(__half2*)&v2.y); acc.z = fmaf(w2, f.x, acc.z); acc.w = fmaf(w2, f.y, acc.w);
        f = __half22float2(*(__half2*)&v3.x); acc.x = fmaf(w3, f.x, acc.x); acc.y = fmaf(w3, f.y, acc.y);
        f = __half22float2(*(__half2*)&v3.y); acc.z = fmaf(w3, f.x, acc.z); acc.w = fmaf(w3, f.y, acc.w);
    }
    acc.x *= di; acc.y *= di; acc.z *= di; acc.w *= di;
    ((float4*)agg)[(size_t)warp * 32 + lane] = acc;
}

// ---------------- batch norm statistics ----------------
__global__ __launch_bounds__(128) void k_bnstats(const float* __restrict__ X) {
    __shared__ float red_s[4][DD];
    __shared__ float red_ss[4][DD];
    int tid = threadIdx.x;
    int c4 = tid & 31;
    int q = tid >> 5;
    float4 s = make_float4(0, 0, 0, 0), ss = make_float4(0, 0, 0, 0);
    for (int r = blockIdx.x * 4 + q; r < NN; r += NB_STATS * 4) {
        float4 v = ((const float4*)X)[(size_t)r * 32 + c4];
        s.x += v.x; s.y += v.y; s.z += v.z; s.w += v.w;
        ss.x = fmaf(v.x, v.x, ss.x); ss.y = fmaf(v.y, v.y, ss.y);
        ss.z = fmaf(v.z, v.z, ss.z); ss.w = fmaf(v.w, v.w, ss.w);
    }
    red_s[q][c4 * 4 + 0] = s.x; red_s[q][c4 * 4 + 1] = s.y;
    red_s[q][c4 * 4 + 2] = s.z; red_s[q][c4 * 4 + 3] = s.w;
    red_ss[q][c4 * 4 + 0] = ss.x; red_ss[q][c4 * 4 + 1] = ss.y;
    red_ss[q][c4 * 4 + 2] = ss.z; red_ss[q][c4 * 4 + 3] = ss.w;
    __syncthreads();
    if (q == 0) {
        #pragma unroll
        for (int k = 0; k < 4; k++) {
            int c = c4 * 4 + k;
            float ts = red_s[0][c] + red_s[1][c] + red_s[2][c] + red_s[3][c];
            float tss = red_ss[0][c] + red_ss[1][c] + red_ss[2][c] + red_ss[3][c];
            g_part[blockIdx.x * (2 * DD) + c] = ts;
            g_part[blockIdx.x * (2 * DD) + DD + c] = tss;
        }
    }
}
__global__ void k_bnfinish(const float* __restrict__ gamma, const float* __restrict__ beta) {
    int c = threadIdx.x;
    float s = 0.f, ss = 0.f;
    for (int b = 0; b < NB_STATS; b++) {
        s += g_part[b * (2 * DD) + c];
        ss += g_part[b * (2 * DD) + DD + c];
    }
    float mean = s * (1.0f / NN);
    float var = ss * (1.0f / NN) - mean * mean;
    float r = rsqrtf(var + EPSV);
    float sc = r * gamma[c];
    g_scale[c] = sc;
    g_shift[c] = fmaf(-mean, sc, beta[c]);
}

// ---------------- final: BN2 + residual + leakyrelu ----------------
__global__ void k_final(const float* __restrict__ agg, const float* __restrict__ x,
                        float* __restrict__ out) {
    int i = blockIdx.x * blockDim.x + threadIdx.x;
    if (i >= NN * DD / 4) return;
    int c = (i & 31) * 4;
    float4 v = ((const float4*)agg)[i];
    float4 xr = ((const float4*)x)[i];
    float y;
    y = fmaf(v.x, g_scale[c + 0], g_shift[c + 0]) + xr.x; v.x = y > 0.f ? y : NEG * y;
    y = fmaf(v.y, g_scale[c + 1], g_shift[c + 1]) + xr.y; v.y = y > 0.f ? y : NEG * y;
    y = fmaf(v.z, g_scale[c + 2], g_shift[c + 2]) + xr.z; v.z = y > 0.f ? y : NEG * y;
    y = fmaf(v.w, g_scale[c + 3], g_shift[c + 3]) + xr.w; v.w = y > 0.f ? y : NEG * y;
    ((float4*)out)[i] = v;
}

// ---------------- launch ----------------
extern "C" void kernel_launch(void* const* d_in, const int* in_sizes, int n_in,
                              void* d_out, int out_size) {
    const float* x   = (const float*)d_in[0];
    const int*   ei  = (const int*)d_in[1];
    const int*   src = ei;
    const int*   dst = ei + EE;
    const float* W1  = (const float*)d_in[2];
    // b1 = d_in[3]: cancels inside BatchNorm
    const float* g1  = (const float*)d_in[4];
    const float* be1 = (const float*)d_in[5];
    const float* W2  = (const float*)d_in[6];
    // b2 = d_in[7]: cancels likewise
    const float* g2  = (const float*)d_in[8];
    const float* be2 = (const float*)d_in[9];
    float* out = (float*)d_out;

    __half* p_h = nullptr;
    float* p_buf = nullptr;
    uint2 *p_w1hi, *p_w1lo, *p_w2hi, *p_w2lo;
    cudaGetSymbolAddress((void**)&p_h, g_h);
    cudaGetSymbolAddress((void**)&p_buf, g_buf);
    cudaGetSymbolAddress((void**)&p_w1hi, g_w1hi);
    cudaGetSymbolAddress((void**)&p_w1lo, g_w1lo);
    cudaGetSymbolAddress((void**)&p_w2hi, g_w2hi);
    cudaGetSymbolAddress((void**)&p_w2lo, g_w2lo);

    cudaFuncSetAttribute(k_gemm_mma<false>, cudaFuncAttributeMaxDynamicSharedMemorySize, SMEMG);
    cudaFuncSetAttribute(k_gemm_mma<true>, cudaFuncAttributeMaxDynamicSharedMemorySize, SMEMG);

    // weight prep + graph preprocessing
    k_prepw<<<16, 256>>>(W1, p_w1hi, p_w1lo);
    k_prepw<<<16, 256>>>(W2, p_w2hi, p_w2lo);
    k_zero<<<(NN + 255) / 256, 256>>>();
    k_hist<<<(EE / 4 + 255) / 256, 256>>>(dst);
    k_scan1<<<SCAN_BLK, 1024>>>();
    k_scan2<<<1, 128>>>();
    k_scan3<<<SCAN_BLK, 1024>>>();
    k_scatter<<<2048, 256>>>(src, dst);

    // layer 1
    k_gemm_mma<false><<<(NN + 127) / 128, 256, SMEMG>>>(x, p_w1hi, p_w1lo, p_h);
    k_agg<<<(NN + 7) / 8, 256>>>(p_h, p_buf);
    k_bnstats<<<NB_STATS, 128>>>(p_buf);
    k_bnfinish<<<1, DD>>>(g1, be1);

    // layer 2 (BN1+act fused into GEMM2 A-load)
    k_gemm_mma<true><<<(NN + 127) / 128, 256, SMEMG>>>(p_buf, p_w2hi, p_w2lo, p_h);
    k_agg<<<(NN + 7) / 8, 256>>>(p_h, p_buf);
    k_bnstats<<<NB_STATS, 128>>>(p_buf);
    k_bnfinish<<<1, DD>>>(g2, be2);
    k_final<<<(NN * DD / 4 + 255) / 256, 256>>>(p_buf, x, out);
}

// round 6
// speedup vs baseline: 1.7718x; 1.0587x over previous
#include <cuda_runtime.h>
#include <cuda_fp16.h>
#include <stdint.h>

#define NN 100000
#define DD 128
#define EE 1600000
#define NEG 0.01f
#define EPSV 1e-5f
#define NB_STATS 512
#define SCAN_BLK 98   // ceil(100000/1024)

// ---------------- device scratch (no allocations allowed) ----------------
__device__ __half g_h[(size_t)NN * DD];    // GEMM output (h1 / h2), fp16
__device__ __half g_buf[(size_t)NN * DD];  // aggregation output, fp16
__device__ int   g_cnt[NN];
__device__ int   g_off[NN + 1];
__device__ int   g_wpos[NN];
__device__ int   g_bsum[SCAN_BLK];
__device__ int   g_boff[SCAN_BLK];
__device__ uint2 g_edge[EE];              // {src, bits(dinv[src])} grouped by dst
__device__ float g_dinv[NN];
__device__ float g_part[NB_STATS * 2 * DD];
__device__ float g_scale[DD];
__device__ float g_shift[DD];
// W pre-split to fp16 hi/lo as per-thread mma-fragment records:
// record (kb,nf), lane: .x = {W[k0][n],W[k0+1][n]}, .y = {W[k0+8][n],W[k0+9][n]}
// with k0 = kb*16 + 2*(lane%4), n = nf*8 + lane/4.
__device__ __align__(16) uint2 g_w1hi[4096];
__device__ __align__(16) uint2 g_w1lo[4096];
__device__ __align__(16) uint2 g_w2hi[4096];
__device__ __align__(16) uint2 g_w2lo[4096];

// ---------------- helpers ----------------
__device__ __forceinline__ uint32_t packh2(__half a, __half b) {
    __half2 t = __halves2half2(a, b);
    return *(uint32_t*)&t;
}
__device__ __forceinline__ void splith2(float x, float y, uint32_t& hi, uint32_t& lo) {
    __half hx = __float2half_rn(x);
    __half hy = __float2half_rn(y);
    float rx = x - __half2float(hx);
    float ry = y - __half2float(hy);
    hi = packh2(hx, hy);
    lo = packh2(__float2half_rn(rx), __float2half_rn(ry));
}
__device__ __forceinline__ void mma16816h(float4& d, const uint32_t a0, const uint32_t a1,
                                          const uint32_t a2, const uint32_t a3,
                                          const uint32_t b0, const uint32_t b1) {
    asm volatile(
        "mma.sync.aligned.m16n8k16.row.col.f32.f16.f16.f32 "
        "{%0,%1,%2,%3}, {%4,%5,%6,%7}, {%8,%9}, {%0,%1,%2,%3};\n"
        : "+f"(d.x), "+f"(d.y), "+f"(d.z), "+f"(d.w)
        : "r"(a0), "r"(a1), "r"(a2), "r"(a3), "r"(b0), "r"(b1));
}

// ---------------- W prep: split fp32 W -> per-thread fp16 frag records ----------
__global__ void k_prepw(const float* __restrict__ W, uint2* __restrict__ bhi,
                        uint2* __restrict__ blo) {
    int i = blockIdx.x * blockDim.x + threadIdx.x;   // 0..4095
    if (i >= 4096) return;
    int lane = i & 31, rec = i >> 5;
    int kb = rec >> 4, nf = rec & 15;
    int g = lane >> 2, tig = lane & 3;
    int k0 = kb * 16 + 2 * tig;
    int n = nf * 8 + g;
    float w00 = W[(k0 + 0) * DD + n];
    float w01 = W[(k0 + 1) * DD + n];
    float w08 = W[(k0 + 8) * DD + n];
    float w09 = W[(k0 + 9) * DD + n];
    uint32_t h0, l0, h1, l1;
    splith2(w00, w01, h0, l0);
    splith2(w08, w09, h1, l1);
    bhi[i] = make_uint2(h0, h1);
    blo[i] = make_uint2(l0, l1);
}

// ---------------- graph preprocessing ----------------
__global__ void k_zero() {
    int i = blockIdx.x * blockDim.x + threadIdx.x;
    if (i < NN) g_cnt[i] = 0;
}
__global__ void k_hist(const int* __restrict__ dst) {
    int i = blockIdx.x * blockDim.x + threadIdx.x;
    if (i < EE / 4) {
        int4 d = ((const int4*)dst)[i];
        atomicAdd(&g_cnt[d.x], 1);
        atomicAdd(&g_cnt[d.y], 1);
        atomicAdd(&g_cnt[d.z], 1);
        atomicAdd(&g_cnt[d.w], 1);
    }
}
__global__ __launch_bounds__(1024) void k_scan1() {
    __shared__ int wsum[32];
    int tid = threadIdx.x, lane = tid & 31, wid = tid >> 5;
    int i = blockIdx.x * 1024 + tid;
    int v = (i < NN) ? g_cnt[i] : 0;
    if (i < NN) g_dinv[i] = rsqrtf((float)v + 1.0f);
    int x = v;
    #pragma unroll
    for (int s = 1; s < 32; s <<= 1) {
        int t = __shfl_up_sync(0xFFFFFFFFu, x, s);
        if (lane >= s) x += t;
    }
    if (lane == 31) wsum[wid] = x;
    __syncthreads();
    if (wid == 0) {
        int y = wsum[lane];
        #pragma unroll
        for (int s = 1; s < 32; s <<= 1) {
            int t = __shfl_up_sync(0xFFFFFFFFu, y, s);
            if (lane >= s) y += t;
        }
        wsum[lane] = y;
    }
    __syncthreads();
    int incl = x + (wid > 0 ? wsum[wid - 1] : 0);
    if (i < NN) g_off[i] = incl - v;
    if (tid == 1023) g_bsum[blockIdx.x] = incl;
}
__global__ void k_scan2() {
    __shared__ int ws[4];
    int tid = threadIdx.x, lane = tid & 31, wid = tid >> 5;
    int v = (tid < SCAN_BLK) ? g_bsum[tid] : 0;
    int x = v;
    #pragma unroll
    for (int s = 1; s < 32; s <<= 1) {
        int t = __shfl_up_sync(0xFFFFFFFFu, x, s);
        if (lane >= s) x += t;
    }
    if (lane == 31) ws[wid] = x;
    __syncthreads();
    int add = 0;
    for (int w = 0; w < wid; w++) add += ws[w];
    int incl = x + add;
    if (tid < SCAN_BLK) g_boff[tid] = incl - v;
    if (tid == 127) g_off[NN] = incl;
}
__global__ __launch_bounds__(1024) void k_scan3() {
    int i = blockIdx.x * 1024 + threadIdx.x;
    if (i < NN) {
        int o = g_off[i] + g_boff[blockIdx.x];
        g_off[i] = o;
        g_wpos[i] = o;
    }
}
__global__ void k_scatter(const int* __restrict__ src, const int* __restrict__ dst) {
    for (int e = blockIdx.x * blockDim.x + threadIdx.x; e < EE; e += gridDim.x * blockDim.x) {
        int s = src[e];
        int d = dst[e];
        int p = atomicAdd(&g_wpos[d], 1);
        g_edge[p] = make_uint2((uint32_t)s, __float_as_uint(g_dinv[s]));
    }
}

// ---------------- GEMM layer 1: C[N,128](fp16) = fp16(A_fp32) @ W (fp16 2-term) --
#define SMEMG (65536 + 1024)
__global__ __launch_bounds__(256, 2) void k_gemm_l1(const float* __restrict__ A,
                                                    const uint2* __restrict__ Bhi,
                                                    const uint2* __restrict__ Blo,
                                                    __half* __restrict__ C) {
    extern __shared__ unsigned char sm[];
    uint2* sWhi = (uint2*)sm;                     // 32KB
    uint2* sWlo = (uint2*)(sm + 32768);           // 32KB
    const int tid = threadIdx.x;
    #pragma unroll
    for (int i = 0; i < 16; i++) {
        sWhi[tid + i * 256] = Bhi[tid + i * 256];
        sWlo[tid + i * 256] = Blo[tid + i * 256];
    }
    __syncthreads();

    const int w = tid >> 5, lane = tid & 31;
    const int g = lane >> 2, tig = lane & 3;
    const int row0 = blockIdx.x * 128 + w * 16 + g;
    const int row8 = row0 + 8;
    const bool ok0 = row0 < NN, ok8 = row8 < NN;

    float4 acc[16];
    #pragma unroll
    for (int nf = 0; nf < 16; nf++) acc[nf] = make_float4(0.f, 0.f, 0.f, 0.f);

    for (int kb = 0; kb < 8; kb++) {
        const int c0 = kb * 16 + tig * 2;
        const int c1 = c0 + 8;
        float2 v00 = ok0 ? *(const float2*)(A + (size_t)row0 * DD + c0) : make_float2(0.f, 0.f);
        float2 v01 = ok0 ? *(const float2*)(A + (size_t)row0 * DD + c1) : make_float2(0.f, 0.f);
        float2 v10 = ok8 ? *(const float2*)(A + (size_t)row8 * DD + c0) : make_float2(0.f, 0.f);
        float2 v11 = ok8 ? *(const float2*)(A + (size_t)row8 * DD + c1) : make_float2(0.f, 0.f);
        uint32_t a0, a1, a2, a3;
        {
            __half2 t;
            t = __floats2half2_rn(v00.x, v00.y); a0 = *(uint32_t*)&t;
            t = __floats2half2_rn(v10.x, v10.y); a1 = *(uint32_t*)&t;
            t = __floats2half2_rn(v01.x, v01.y); a2 = *(uint32_t*)&t;
            t = __floats2half2_rn(v11.x, v11.y); a3 = *(uint32_t*)&t;
        }
        const uint2* bh = sWhi + (kb * 16) * 32 + lane;
        const uint2* bl = sWlo + (kb * 16) * 32 + lane;
        #pragma unroll
        for (int nf = 0; nf < 16; nf++) {
            uint2 bhv = bh[nf * 32];
            uint2 blv = bl[nf * 32];
            mma16816h(acc[nf], a0, a1, a2, a3, bhv.x, bhv.y);
            mma16816h(acc[nf], a0, a1, a2, a3, blv.x, blv.y);
        }
    }
    if (ok0) {
        #pragma unroll
        for (int nf = 0; nf < 16; nf++) {
            __half2 o = __floats2half2_rn(acc[nf].x, acc[nf].y);
            *(__half2*)(C + (size_t)row0 * DD + nf * 8 + tig * 2) = o;
        }
    }
    if (ok8) {
        #pragma unroll
        for (int nf = 0; nf < 16; nf++) {
            __half2 o = __floats2half2_rn(acc[nf].z, acc[nf].w);
            *(__half2*)(C + (size_t)row8 * DD + nf * 8 + tig * 2) = o;
        }
    }
}

// ---------------- GEMM layer 2: A fp16 + BN1+leakyrelu fused on load -------------
__global__ __launch_bounds__(256, 2) void k_gemm_l2(const __half* __restrict__ A,
                                                    const uint2* __restrict__ Bhi,
                                                    const uint2* __restrict__ Blo,
                                                    __half* __restrict__ C) {
    extern __shared__ unsigned char sm[];
    uint2* sWhi = (uint2*)sm;
    uint2* sWlo = (uint2*)(sm + 32768);
    float* sSc = (float*)(sm + 65536);
    float* sSh = (float*)(sm + 66048);
    const int tid = threadIdx.x;
    #pragma unroll
    for (int i = 0; i < 16; i++) {
        sWhi[tid + i * 256] = Bhi[tid + i * 256];
        sWlo[tid + i * 256] = Blo[tid + i * 256];
    }
    if (tid < 128) {
        sSc[tid] = g_scale[tid];
        sSh[tid] = g_shift[tid];
    }
    __syncthreads();

    const int w = tid >> 5, lane = tid & 31;
    const int g = lane >> 2, tig = lane & 3;
    const int row0 = blockIdx.x * 128 + w * 16 + g;
    const int row8 = row0 + 8;
    const bool ok0 = row0 < NN, ok8 = row8 < NN;
    const uint32_t* __restrict__ Ah2 = (const uint32_t*)A;   // half2 view

    float4 acc[16];
    #pragma unroll
    for (int nf = 0; nf < 16; nf++) acc[nf] = make_float4(0.f, 0.f, 0.f, 0.f);

    for (int kb = 0; kb < 8; kb++) {
        const int c0 = kb * 16 + tig * 2;
        const int c1 = c0 + 8;
        uint32_t r00 = ok0 ? Ah2[(size_t)row0 * 64 + (c0 >> 1)] : 0u;
        uint32_t r01 = ok0 ? Ah2[(size_t)row0 * 64 + (c1 >> 1)] : 0u;
        uint32_t r10 = ok8 ? Ah2[(size_t)row8 * 64 + (c0 >> 1)] : 0u;
        uint32_t r11 = ok8 ? Ah2[(size_t)row8 * 64 + (c1 >> 1)] : 0u;
        float2 sc0 = *(const float2*)&sSc[c0], sh0 = *(const float2*)&sSh[c0];
        float2 sc1 = *(const float2*)&sSc[c1], sh1 = *(const float2*)&sSh[c1];
        uint32_t a0, a1, a2, a3;
        {
            float2 f; float y0, y1; __half2 t;
            f = __half22float2(*(__half2*)&r00);
            y0 = fmaf(f.x, sc0.x, sh0.x); y0 = y0 > 0.f ? y0 : NEG * y0;
            y1 = fmaf(f.y, sc0.y, sh0.y); y1 = y1 > 0.f ? y1 : NEG * y1;
            t = __floats2half2_rn(y0, y1); a0 = *(uint32_t*)&t;
            f = __half22float2(*(__half2*)&r10);
            y0 = fmaf(f.x, sc0.x, sh0.x); y0 = y0 > 0.f ? y0 : NEG * y0;
            y1 = fmaf(f.y, sc0.y, sh0.y); y1 = y1 > 0.f ? y1 : NEG * y1;
            t = __floats2half2_rn(y0, y1); a1 = *(uint32_t*)&t;
            f = __half22float2(*(__half2*)&r01);
            y0 = fmaf(f.x, sc1.x, sh1.x); y0 = y0 > 0.f ? y0 : NEG * y0;
            y1 = fmaf(f.y, sc1.y, sh1.y); y1 = y1 > 0.f ? y1 : NEG * y1;
            t = __floats2half2_rn(y0, y1); a2 = *(uint32_t*)&t;
            f = __half22float2(*(__half2*)&r11);
            y0 = fmaf(f.x, sc1.x, sh1.x); y0 = y0 > 0.f ? y0 : NEG * y0;
            y1 = fmaf(f.y, sc1.y, sh1.y); y1 = y1 > 0.f ? y1 : NEG * y1;
            t = __floats2half2_rn(y0, y1); a3 = *(uint32_t*)&t;
        }
        const uint2* bh = sWhi + (kb * 16) * 32 + lane;
        const uint2* bl = sWlo + (kb * 16) * 32 + lane;
        #pragma unroll
        for (int nf = 0; nf < 16; nf++) {
            uint2 bhv = bh[nf * 32];
            uint2 blv = bl[nf * 32];
            mma16816h(acc[nf], a0, a1, a2, a3, bhv.x, bhv.y);
            mma16816h(acc[nf], a0, a1, a2, a3, blv.x, blv.y);
        }
    }
    if (ok0) {
        #pragma unroll
        for (int nf = 0; nf < 16; nf++) {
            __half2 o = __floats2half2_rn(acc[nf].x, acc[nf].y);
            *(__half2*)(C + (size_t)row0 * DD + nf * 8 + tig * 2) = o;
        }
    }
    if (ok8) {
        #pragma unroll
        for (int nf = 0; nf < 16; nf++) {
            __half2 o = __floats2half2_rn(acc[nf].z, acc[nf].w);
            *(__half2*)(C + (size_t)row8 * DD + nf * 8 + tig * 2) = o;
        }
    }
}

// ---------------- per-node CSR aggregation (one warp per dst node) --------
// fp16 gathers, fp32 accumulate, fp16 output
__global__ void k_agg(const __half* __restrict__ h, __half* __restrict__ agg) {
    int warp = (blockIdx.x * blockDim.x + threadIdx.x) >> 5;
    int lane = threadIdx.x & 31;
    if (warp >= NN) return;
    const uint2* __restrict__ hp = (const uint2*)h;   // 4 halves per lane
    float di = g_dinv[warp];
    uint2 sv = hp[(size_t)warp * 32 + lane];
    float2 a01 = __half22float2(*(__half2*)&sv.x);
    float2 a23 = __half22float2(*(__half2*)&sv.y);
    float4 acc = make_float4(a01.x * di, a01.y * di, a23.x * di, a23.y * di);
    int e0 = g_off[warp], e1 = g_off[warp + 1];
    for (int e = e0; e < e1; e += 4) {
        int i1 = min(e + 1, e1 - 1), i2 = min(e + 2, e1 - 1), i3 = min(e + 3, e1 - 1);
        uint2 r0 = g_edge[e], r1 = g_edge[i1], r2 = g_edge[i2], r3 = g_edge[i3];
        float w0 = __uint_as_float(r0.y);
        float w1 = (e + 1 < e1) ? __uint_as_float(r1.y) : 0.0f;
        float w2 = (e + 2 < e1) ? __uint_as_float(r2.y) : 0.0f;
        float w3 = (e + 3 < e1) ? __uint_as_float(r3.y) : 0.0f;
        uint2 v0 = hp[(size_t)r0.x * 32 + lane];
        uint2 v1 = hp[(size_t)r1.x * 32 + lane];
        uint2 v2 = hp[(size_t)r2.x * 32 + lane];
        uint2 v3 = hp[(size_t)r3.x * 32 + lane];
        float2 f;
        f = __half22float2(*(__half2*)&v0.x); acc.x = fmaf(w0, f.x, acc.x); acc.y = fmaf(w0, f.y, acc.y);
        f = __half22float2(*(__half2*)&v0.y); acc.z = fmaf(w0, f.x, acc.z); acc.w = fmaf(w0, f.y, acc.w);
        f = __half22float2(*(__half2*)&v1.x); acc.x = fmaf(w1, f.x, acc.x); acc.y = fmaf(w1, f.y, acc.y);
        f = __half22float2(*(__half2*)&v1.y); acc.z = fmaf(w1, f.x, acc.z); acc.w = fmaf(w1, f.y, acc.w);
        f = __half22float2(*(__half2*)&v2.x); acc.x = fmaf(w2, f.x, acc.x); acc.y = fmaf(w2, f.y, acc.y);
        f = __half22float2(*(__half2*)&v2.y); acc.z = fmaf(w2, f.x, acc.z); acc.w = fmaf(w2, f.y, acc.w);
        f = __half22float2(*(__half2*)&v3.x); acc.x = fmaf(w3, f.x, acc.x); acc.y = fmaf(w3, f.y, acc.y);
        f = __half22float2(*(__half2*)&v3.y); acc.z = fmaf(w3, f.x, acc.z); acc.w = fmaf(w3, f.y, acc.w);
    }
    acc.x *= di; acc.y *= di; acc.z *= di; acc.w *= di;
    __half2 o01 = __floats2half2_rn(acc.x, acc.y);
    __half2 o23 = __floats2half2_rn(acc.z, acc.w);
    ((uint2*)agg)[(size_t)warp * 32 + lane] = make_uint2(*(uint32_t*)&o01, *(uint32_t*)&o23);
}

// ---------------- batch norm statistics (fp16 input, fp32 sums) ----------------
__global__ __launch_bounds__(128) void k_bnstats(const __half* __restrict__ X) {
    __shared__ float red_s[4][DD];
    __shared__ float red_ss[4][DD];
    int tid = threadIdx.x;
    int c4 = tid & 31;
    int q = tid >> 5;
    const uint2* Xp = (const uint2*)X;
    float4 s = make_float4(0, 0, 0, 0), ss = make_float4(0, 0, 0, 0);
    for (int r = blockIdx.x * 4 + q; r < NN; r += NB_STATS * 4) {
        uint2 u = Xp[(size_t)r * 32 + c4];
        float2 f01 = __half22float2(*(__half2*)&u.x);
        float2 f23 = __half22float2(*(__half2*)&u.y);
        s.x += f01.x; s.y += f01.y; s.z += f23.x; s.w += f23.y;
        ss.x = fmaf(f01.x, f01.x, ss.x); ss.y = fmaf(f01.y, f01.y, ss.y);
        ss.z = fmaf(f23.x, f23.x, ss.z); ss.w = fmaf(f23.y, f23.y, ss.w);
    }
    red_s[q][c4 * 4 + 0] = s.x; red_s[q][c4 * 4 + 1] = s.y;
    red_s[q][c4 * 4 + 2] = s.z; red_s[q][c4 * 4 + 3] = s.w;
    red_ss[q][c4 * 4 + 0] = ss.x; red_ss[q][c4 * 4 + 1] = ss.y;
    red_ss[q][c4 * 4 + 2] = ss.z; red_ss[q][c4 * 4 + 3] = ss.w;
    __syncthreads();
    if (q == 0) {
        #pragma unroll
        for (int k = 0; k < 4; k++) {
            int c = c4 * 4 + k;
            float ts = red_s[0][c] + red_s[1][c] + red_s[2][c] + red_s[3][c];
            float tss = red_ss[0][c] + red_ss[1][c] + red_ss[2][c] + red_ss[3][c];
            g_part[blockIdx.x * (2 * DD) + c] = ts;
            g_part[blockIdx.x * (2 * DD) + DD + c] = tss;
        }
    }
}
__global__ void k_bnfinish(const float* __restrict__ gamma, const float* __restrict__ beta) {
    int c = threadIdx.x;
    float s = 0.f, ss = 0.f;
    for (int b = 0; b < NB_STATS; b++) {
        s += g_part[b * (2 * DD) + c];
        ss += g_part[b * (2 * DD) + DD + c];
    }
    float mean = s * (1.0f / NN);
    float var = ss * (1.0f / NN) - mean * mean;
    float r = rsqrtf(var + EPSV);
    float sc = r * gamma[c];
    g_scale[c] = sc;
    g_shift[c] = fmaf(-mean, sc, beta[c]);
}

// ---------------- final: BN2 + residual + leakyrelu (fp32 out) ----------------
__global__ void k_final(const __half* __restrict__ agg, const float* __restrict__ x,
                        float* __restrict__ out) {
    int i = blockIdx.x * blockDim.x + threadIdx.x;   // float4 / uint2 index
    if (i >= NN * DD / 4) return;
    int c = (i & 31) * 4;
    uint2 u = ((const uint2*)agg)[i];
    float2 v01 = __half22float2(*(__half2*)&u.x);
    float2 v23 = __half22float2(*(__half2*)&u.y);
    float4 xr = ((const float4*)x)[i];
    float4 o;
    float y;
    y = fmaf(v01.x, g_scale[c + 0], g_shift[c + 0]) + xr.x; o.x = y > 0.f ? y : NEG * y;
    y = fmaf(v01.y, g_scale[c + 1], g_shift[c + 1]) + xr.y; o.y = y > 0.f ? y : NEG * y;
    y = fmaf(v23.x, g_scale[c + 2], g_shift[c + 2]) + xr.z; o.z = y > 0.f ? y : NEG * y;
    y = fmaf(v23.y, g_scale[c + 3], g_shift[c + 3]) + xr.w; o.w = y > 0.f ? y : NEG * y;
    ((float4*)out)[i] = o;
}

// ---------------- launch ----------------
extern "C" void kernel_launch(void* const* d_in, const int* in_sizes, int n_in,
                              void* d_out, int out_size) {
    const float* x   = (const float*)d_in[0];
    const int*   ei  = (const int*)d_in[1];
    const int*   src = ei;
    const int*   dst = ei + EE;
    const float* W1  = (const float*)d_in[2];
    // b1 = d_in[3]: cancels inside BatchNorm
    const float* g1  = (const float*)d_in[4];
    const float* be1 = (const float*)d_in[5];
    const float* W2  = (const float*)d_in[6];
    // b2 = d_in[7]: cancels likewise
    const float* g2  = (const float*)d_in[8];
    const float* be2 = (const float*)d_in[9];
    float* out = (float*)d_out;

    __half* p_h = nullptr;
    __half* p_buf = nullptr;
    uint2 *p_w1hi, *p_w1lo, *p_w2hi, *p_w2lo;
    cudaGetSymbolAddress((void**)&p_h, g_h);
    cudaGetSymbolAddress((void**)&p_buf, g_buf);
    cudaGetSymbolAddress((void**)&p_w1hi, g_w1hi);
    cudaGetSymbolAddress((void**)&p_w1lo, g_w1lo);
    cudaGetSymbolAddress((void**)&p_w2hi, g_w2hi);
    cudaGetSymbolAddress((void**)&p_w2lo, g_w2lo);

    cudaFuncSetAttribute(k_gemm_l1, cudaFuncAttributeMaxDynamicSharedMemorySize, SMEMG);
    cudaFuncSetAttribute(k_gemm_l2, cudaFuncAttributeMaxDynamicSharedMemorySize, SMEMG);

    // weight prep + graph preprocessing
    k_prepw<<<16, 256>>>(W1, p_w1hi, p_w1lo);
    k_prepw<<<16, 256>>>(W2, p_w2hi, p_w2lo);
    k_zero<<<(NN + 255) / 256, 256>>>();
    k_hist<<<(EE / 4 + 255) / 256, 256>>>(dst);
    k_scan1<<<SCAN_BLK, 1024>>>();
    k_scan2<<<1, 128>>>();
    k_scan3<<<SCAN_BLK, 1024>>>();
    k_scatter<<<2048, 256>>>(src, dst);

    // layer 1
    k_gemm_l1<<<(NN + 127) / 128, 256, SMEMG>>>(x, p_w1hi, p_w1lo, p_h);
    k_agg<<<(NN + 7) / 8, 256>>>(p_h, p_buf);
    k_bnstats<<<NB_STATS, 128>>>(p_buf);
    k_bnfinish<<<1, DD>>>(g1, be1);

    // layer 2 (BN1+act fused into GEMM2 A-load)
    k_gemm_l2<<<(NN + 127) / 128, 256, SMEMG>>>(p_buf, p_w2hi, p_w2lo, p_h);
    k_agg<<<(NN + 7) / 8, 256>>>(p_h, p_buf);
    k_bnstats<<<NB_STATS, 128>>>(p_buf);
    k_bnfinish<<<1, DD>>>(g2, be2);
    k_final<<<(NN * DD / 4 + 255) / 256, 256>>>(p_buf, x, out);
}

// round 7
// speedup vs baseline: 1.9531x; 1.1023x over previous
#include <cuda_runtime.h>
#include <cuda_fp16.h>
#include <stdint.h>

#define NN 100000
#define DD 128
#define EE 1600000
#define NEG 0.01f
#define EPSV 1e-5f
#define NB_STATS 512
#define SCAN_BLK 98   // ceil(100000/1024)

// ---------------- device scratch (no allocations allowed) ----------------
__device__ __half g_h[(size_t)NN * DD];    // GEMM output pre-scaled by dinv (h')
__device__ __half g_buf[(size_t)NN * DD];  // aggregation output, fp16
__device__ int   g_cnt[NN];
__device__ int   g_off[NN + 1];
__device__ int   g_wpos[NN];
__device__ int   g_bsum[SCAN_BLK];
__device__ int   g_boff[SCAN_BLK];
__device__ int   g_ssrc[EE];              // src ids grouped by dst (CSR)
__device__ float g_dinv[NN];
__device__ float g_part[NB_STATS * 2 * DD];
__device__ float g_scale[DD];
__device__ float g_shift[DD];
// W pre-split to fp16 hi/lo as per-thread mma-fragment records
__device__ __align__(16) uint2 g_w1hi[4096];
__device__ __align__(16) uint2 g_w1lo[4096];
__device__ __align__(16) uint2 g_w2hi[4096];
__device__ __align__(16) uint2 g_w2lo[4096];

// ---------------- helpers ----------------
__device__ __forceinline__ uint32_t packh2(__half a, __half b) {
    __half2 t = __halves2half2(a, b);
    return *(uint32_t*)&t;
}
__device__ __forceinline__ void splith2(float x, float y, uint32_t& hi, uint32_t& lo) {
    __half hx = __float2half_rn(x);
    __half hy = __float2half_rn(y);
    float rx = x - __half2float(hx);
    float ry = y - __half2float(hy);
    hi = packh2(hx, hy);
    lo = packh2(__float2half_rn(rx), __float2half_rn(ry));
}
__device__ __forceinline__ void mma16816h(float4& d, const uint32_t a0, const uint32_t a1,
                                          const uint32_t a2, const uint32_t a3,
                                          const uint32_t b0, const uint32_t b1) {
    asm volatile(
        "mma.sync.aligned.m16n8k16.row.col.f32.f16.f16.f32 "
        "{%0,%1,%2,%3}, {%4,%5,%6,%7}, {%8,%9}, {%0,%1,%2,%3};\n"
        : "+f"(d.x), "+f"(d.y), "+f"(d.z), "+f"(d.w)
        : "r"(a0), "r"(a1), "r"(a2), "r"(a3), "r"(b0), "r"(b1));
}

// ---------------- W prep: both matrices in one launch ----------------
__global__ void k_prepw(const float* __restrict__ W1, const float* __restrict__ W2) {
    int i = blockIdx.x * blockDim.x + threadIdx.x;   // 0..8191
    if (i >= 8192) return;
    const float* W = (i < 4096) ? W1 : W2;
    uint2* bhi = (i < 4096) ? g_w1hi : g_w2hi;
    uint2* blo = (i < 4096) ? g_w1lo : g_w2lo;
    int r = i & 4095;
    int lane = r & 31, rec = r >> 5;
    int kb = rec >> 4, nf = rec & 15;
    int g = lane >> 2, tig = lane & 3;
    int k0 = kb * 16 + 2 * tig;
    int n = nf * 8 + g;
    float w00 = W[(k0 + 0) * DD + n];
    float w01 = W[(k0 + 1) * DD + n];
    float w08 = W[(k0 + 8) * DD + n];
    float w09 = W[(k0 + 9) * DD + n];
    uint32_t h0, l0, h1, l1;
    splith2(w00, w01, h0, l0);
    splith2(w08, w09, h1, l1);
    bhi[r] = make_uint2(h0, h1);
    blo[r] = make_uint2(l0, l1);
}

// ---------------- graph preprocessing ----------------
__global__ void k_zero() {
    int i = blockIdx.x * blockDim.x + threadIdx.x;
    if (i < NN) g_cnt[i] = 0;
}
__global__ void k_hist(const int* __restrict__ dst) {
    int i = blockIdx.x * blockDim.x + threadIdx.x;
    if (i < EE / 4) {
        int4 d = ((const int4*)dst)[i];
        atomicAdd(&g_cnt[d.x], 1);
        atomicAdd(&g_cnt[d.y], 1);
        atomicAdd(&g_cnt[d.z], 1);
        atomicAdd(&g_cnt[d.w], 1);
    }
}
__global__ __launch_bounds__(1024) void k_scan1() {
    __shared__ int wsum[32];
    int tid = threadIdx.x, lane = tid & 31, wid = tid >> 5;
    int i = blockIdx.x * 1024 + tid;
    int v = (i < NN) ? g_cnt[i] : 0;
    if (i < NN) g_dinv[i] = rsqrtf((float)v + 1.0f);
    int x = v;
    #pragma unroll
    for (int s = 1; s < 32; s <<= 1) {
        int t = __shfl_up_sync(0xFFFFFFFFu, x, s);
        if (lane >= s) x += t;
    }
    if (lane == 31) wsum[wid] = x;
    __syncthreads();
    if (wid == 0) {
        int y = wsum[lane];
        #pragma unroll
        for (int s = 1; s < 32; s <<= 1) {
            int t = __shfl_up_sync(0xFFFFFFFFu, y, s);
            if (lane >= s) y += t;
        }
        wsum[lane] = y;
    }
    __syncthreads();
    int incl = x + (wid > 0 ? wsum[wid - 1] : 0);
    if (i < NN) g_off[i] = incl - v;
    if (tid == 1023) g_bsum[blockIdx.x] = incl;
}
__global__ void k_scan2() {
    __shared__ int ws[4];
    int tid = threadIdx.x, lane = tid & 31, wid = tid >> 5;
    int v = (tid < SCAN_BLK) ? g_bsum[tid] : 0;
    int x = v;
    #pragma unroll
    for (int s = 1; s < 32; s <<= 1) {
        int t = __shfl_up_sync(0xFFFFFFFFu, x, s);
        if (lane >= s) x += t;
    }
    if (lane == 31) ws[wid] = x;
    __syncthreads();
    int add = 0;
    for (int w = 0; w < wid; w++) add += ws[w];
    int incl = x + add;
    if (tid < SCAN_BLK) g_boff[tid] = incl - v;
    if (tid == 127) g_off[NN] = incl;
}
__global__ __launch_bounds__(1024) void k_scan3() {
    int i = blockIdx.x * 1024 + threadIdx.x;
    if (i < NN) {
        int o = g_off[i] + g_boff[blockIdx.x];
        g_off[i] = o;
        g_wpos[i] = o;
    }
}
__global__ void k_scatter(const int* __restrict__ src, const int* __restrict__ dst) {
    for (int e = blockIdx.x * blockDim.x + threadIdx.x; e < EE; e += gridDim.x * blockDim.x) {
        int s = src[e];
        int d = dst[e];
        int p = atomicAdd(&g_wpos[d], 1);
        g_ssrc[p] = s;
    }
}

// ---------------- GEMM layer 1: C = dinv_row * (fp16(A) @ W), fp16 out ----------
#define SMEMG (65536 + 1024)
__global__ __launch_bounds__(256, 2) void k_gemm_l1(const float* __restrict__ A,
                                                    const uint2* __restrict__ Bhi,
                                                    const uint2* __restrict__ Blo,
                                                    __half* __restrict__ C) {
    extern __shared__ unsigned char sm[];
    uint2* sWhi = (uint2*)sm;                     // 32KB
    uint2* sWlo = (uint2*)(sm + 32768);           // 32KB
    const int tid = threadIdx.x;
    #pragma unroll
    for (int i = 0; i < 16; i++) {
        sWhi[tid + i * 256] = Bhi[tid + i * 256];
        sWlo[tid + i * 256] = Blo[tid + i * 256];
    }
    __syncthreads();

    const int w = tid >> 5, lane = tid & 31;
    const int g = lane >> 2, tig = lane & 3;
    const int row0 = blockIdx.x * 128 + w * 16 + g;
    const int row8 = row0 + 8;
    const bool ok0 = row0 < NN, ok8 = row8 < NN;

    float4 acc[16];
    #pragma unroll
    for (int nf = 0; nf < 16; nf++) acc[nf] = make_float4(0.f, 0.f, 0.f, 0.f);

    for (int kb = 0; kb < 8; kb++) {
        const int c0 = kb * 16 + tig * 2;
        const int c1 = c0 + 8;
        float2 v00 = ok0 ? *(const float2*)(A + (size_t)row0 * DD + c0) : make_float2(0.f, 0.f);
        float2 v01 = ok0 ? *(const float2*)(A + (size_t)row0 * DD + c1) : make_float2(0.f, 0.f);
        float2 v10 = ok8 ? *(const float2*)(A + (size_t)row8 * DD + c0) : make_float2(0.f, 0.f);
        float2 v11 = ok8 ? *(const float2*)(A + (size_t)row8 * DD + c1) : make_float2(0.f, 0.f);
        uint32_t a0, a1, a2, a3;
        {
            __half2 t;
            t = __floats2half2_rn(v00.x, v00.y); a0 = *(uint32_t*)&t;
            t = __floats2half2_rn(v10.x, v10.y); a1 = *(uint32_t*)&t;
            t = __floats2half2_rn(v01.x, v01.y); a2 = *(uint32_t*)&t;
            t = __floats2half2_rn(v11.x, v11.y); a3 = *(uint32_t*)&t;
        }
        const uint2* bh = sWhi + (kb * 16) * 32 + lane;
        const uint2* bl = sWlo + (kb * 16) * 32 + lane;
        #pragma unroll
        for (int nf = 0; nf < 16; nf++) {
            uint2 bhv = bh[nf * 32];
            uint2 blv = bl[nf * 32];
            mma16816h(acc[nf], a0, a1, a2, a3, bhv.x, bhv.y);
            mma16816h(acc[nf], a0, a1, a2, a3, blv.x, blv.y);
        }
    }
    const float di0 = ok0 ? g_dinv[row0] : 0.f;
    const float di8 = ok8 ? g_dinv[row8] : 0.f;
    if (ok0) {
        #pragma unroll
        for (int nf = 0; nf < 16; nf++) {
            __half2 o = __floats2half2_rn(acc[nf].x * di0, acc[nf].y * di0);
            *(__half2*)(C + (size_t)row0 * DD + nf * 8 + tig * 2) = o;
        }
    }
    if (ok8) {
        #pragma unroll
        for (int nf = 0; nf < 16; nf++) {
            __half2 o = __floats2half2_rn(acc[nf].z * di8, acc[nf].w * di8);
            *(__half2*)(C + (size_t)row8 * DD + nf * 8 + tig * 2) = o;
        }
    }
}

// ---------------- GEMM layer 2: A fp16 + BN1+leakyrelu fused, dinv-scaled out ----
__global__ __launch_bounds__(256, 2) void k_gemm_l2(const __half* __restrict__ A,
                                                    const uint2* __restrict__ Bhi,
                                                    const uint2* __restrict__ Blo,
                                                    __half* __restrict__ C) {
    extern __shared__ unsigned char sm[];
    uint2* sWhi = (uint2*)sm;
    uint2* sWlo = (uint2*)(sm + 32768);
    float* sSc = (float*)(sm + 65536);
    float* sSh = (float*)(sm + 66048);
    const int tid = threadIdx.x;
    #pragma unroll
    for (int i = 0; i < 16; i++) {
        sWhi[tid + i * 256] = Bhi[tid + i * 256];
        sWlo[tid + i * 256] = Blo[tid + i * 256];
    }
    if (tid < 128) {
        sSc[tid] = g_scale[tid];
        sSh[tid] = g_shift[tid];
    }
    __syncthreads();

    const int w = tid >> 5, lane = tid & 31;
    const int g = lane >> 2, tig = lane & 3;
    const int row0 = blockIdx.x * 128 + w * 16 + g;
    const int row8 = row0 + 8;
    const bool ok0 = row0 < NN, ok8 = row8 < NN;
    const uint32_t* __restrict__ Ah2 = (const uint32_t*)A;   // half2 view

    float4 acc[16];
    #pragma unroll
    for (int nf = 0; nf < 16; nf++) acc[nf] = make_float4(0.f, 0.f, 0.f, 0.f);

    for (int kb = 0; kb < 8; kb++) {
        const int c0 = kb * 16 + tig * 2;
        const int c1 = c0 + 8;
        uint32_t r00 = ok0 ? Ah2[(size_t)row0 * 64 + (c0 >> 1)] : 0u;
        uint32_t r01 = ok0 ? Ah2[(size_t)row0 * 64 + (c1 >> 1)] : 0u;
        uint32_t r10 = ok8 ? Ah2[(size_t)row8 * 64 + (c0 >> 1)] : 0u;
        uint32_t r11 = ok8 ? Ah2[(size_t)row8 * 64 + (c1 >> 1)] : 0u;
        float2 sc0 = *(const float2*)&sSc[c0], sh0 = *(const float2*)&sSh[c0];
        float2 sc1 = *(const float2*)&sSc[c1], sh1 = *(const float2*)&sSh[c1];
        uint32_t a0, a1, a2, a3;
        {
            float2 f; float y0, y1; __half2 t;
            f = __half22float2(*(__half2*)&r00);
            y0 = fmaf(f.x, sc0.x, sh0.x); y0 = y0 > 0.f ? y0 : NEG * y0;
            y1 = fmaf(f.y, sc0.y, sh0.y); y1 = y1 > 0.f ? y1 : NEG * y1;
            t = __floats2half2_rn(y0, y1); a0 = *(uint32_t*)&t;
            f = __half22float2(*(__half2*)&r10);
            y0 = fmaf(f.x, sc0.x, sh0.x); y0 = y0 > 0.f ? y0 : NEG * y0;
            y1 = fmaf(f.y, sc0.y, sh0.y); y1 = y1 > 0.f ? y1 : NEG * y1;
            t = __floats2half2_rn(y0, y1); a1 = *(uint32_t*)&t;
            f = __half22float2(*(__half2*)&r01);
            y0 = fmaf(f.x, sc1.x, sh1.x); y0 = y0 > 0.f ? y0 : NEG * y0;
            y1 = fmaf(f.y, sc1.y, sh1.y); y1 = y1 > 0.f ? y1 : NEG * y1;
            t = __floats2half2_rn(y0, y1); a2 = *(uint32_t*)&t;
            f = __half22float2(*(__half2*)&r11);
            y0 = fmaf(f.x, sc1.x, sh1.x); y0 = y0 > 0.f ? y0 : NEG * y0;
            y1 = fmaf(f.y, sc1.y, sh1.y); y1 = y1 > 0.f ? y1 : NEG * y1;
            t = __floats2half2_rn(y0, y1); a3 = *(uint32_t*)&t;
        }
        const uint2* bh = sWhi + (kb * 16) * 32 + lane;
        const uint2* bl = sWlo + (kb * 16) * 32 + lane;
        #pragma unroll
        for (int nf = 0; nf < 16; nf++) {
            uint2 bhv = bh[nf * 32];
            uint2 blv = bl[nf * 32];
            mma16816h(acc[nf], a0, a1, a2, a3, bhv.x, bhv.y);
            mma16816h(acc[nf], a0, a1, a2, a3, blv.x, blv.y);
        }
    }
    const float di0 = ok0 ? g_dinv[row0] : 0.f;
    const float di8 = ok8 ? g_dinv[row8] : 0.f;
    if (ok0) {
        #pragma unroll
        for (int nf = 0; nf < 16; nf++) {
            __half2 o = __floats2half2_rn(acc[nf].x * di0, acc[nf].y * di0);
            *(__half2*)(C + (size_t)row0 * DD + nf * 8 + tig * 2) = o;
        }
    }
    if (ok8) {
        #pragma unroll
        for (int nf = 0; nf < 16; nf++) {
            __half2 o = __floats2half2_rn(acc[nf].z * di8, acc[nf].w * di8);
            *(__half2*)(C + (size_t)row8 * DD + nf * 8 + tig * 2) = o;
        }
    }
}

// ---------------- per-node CSR aggregation (one warp per dst node) --------
// h is pre-scaled by dinv -> weightless gather+add; coalesced edge index loads.
__global__ void k_agg(const __half* __restrict__ h, __half* __restrict__ agg) {
    int warp = (blockIdx.x * blockDim.x + threadIdx.x) >> 5;
    int lane = threadIdx.x & 31;
    if (warp >= NN) return;
    const uint2* __restrict__ hp = (const uint2*)h;   // 4 halves per lane
    float di = g_dinv[warp];
    uint2 sv = hp[(size_t)warp * 32 + lane];          // self (already dinv-scaled)
    float2 a01 = __half22float2(*(__half2*)&sv.x);
    float2 a23 = __half22float2(*(__half2*)&sv.y);
    float4 acc = make_float4(a01.x, a01.y, a23.x, a23.y);
    int e0 = g_off[warp], e1 = g_off[warp + 1];
    for (int base = e0; base < e1; base += 32) {
        int t = base + lane;
        int idx = (t < e1) ? g_ssrc[t] : 0;           // one coalesced LDG per 32 edges
        int cnt = min(32, e1 - base);
        int j = 0;
        for (; j + 4 <= cnt; j += 4) {
            int s0 = __shfl_sync(0xFFFFFFFFu, idx, j);
            int s1 = __shfl_sync(0xFFFFFFFFu, idx, j + 1);
            int s2 = __shfl_sync(0xFFFFFFFFu, idx, j + 2);
            int s3 = __shfl_sync(0xFFFFFFFFu, idx, j + 3);
            uint2 v0 = hp[(size_t)s0 * 32 + lane];
            uint2 v1 = hp[(size_t)s1 * 32 + lane];
            uint2 v2 = hp[(size_t)s2 * 32 + lane];
            uint2 v3 = hp[(size_t)s3 * 32 + lane];
            float2 f;
            f = __half22float2(*(__half2*)&v0.x); acc.x += f.x; acc.y += f.y;
            f = __half22float2(*(__half2*)&v0.y); acc.z += f.x; acc.w += f.y;
            f = __half22float2(*(__half2*)&v1.x); acc.x += f.x; acc.y += f.y;
            f = __half22float2(*(__half2*)&v1.y); acc.z += f.x; acc.w += f.y;
            f = __half22float2(*(__half2*)&v2.x); acc.x += f.x; acc.y += f.y;
            f = __half22float2(*(__half2*)&v2.y); acc.z += f.x; acc.w += f.y;
            f = __half22float2(*(__half2*)&v3.x); acc.x += f.x; acc.y += f.y;
            f = __half22float2(*(__half2*)&v3.y); acc.z += f.x; acc.w += f.y;
        }
        for (; j < cnt; j++) {
            int s = __shfl_sync(0xFFFFFFFFu, idx, j);
            uint2 v = hp[(size_t)s * 32 + lane];
            float2 f;
            f = __half22float2(*(__half2*)&v.x); acc.x += f.x; acc.y += f.y;
            f = __half22float2(*(__half2*)&v.y); acc.z += f.x; acc.w += f.y;
        }
    }
    acc.x *= di; acc.y *= di; acc.z *= di; acc.w *= di;
    __half2 o01 = __floats2half2_rn(acc.x, acc.y);
    __half2 o23 = __floats2half2_rn(acc.z, acc.w);
    ((uint2*)agg)[(size_t)warp * 32 + lane] = make_uint2(*(uint32_t*)&o01, *(uint32_t*)&o23);
}

// ---------------- batch norm statistics (fp16 input, fp32 sums) ----------------
__global__ __launch_bounds__(256) void k_bnstats(const __half* __restrict__ X) {
    __shared__ float red_s[8][DD];
    __shared__ float red_ss[8][DD];
    int tid = threadIdx.x;
    int c4 = tid & 31;   // uint2 column group (4 halves)
    int q = tid >> 5;    // 0..7 row-parallel groups
    const uint2* Xp = (const uint2*)X;
    float4 s = make_float4(0, 0, 0, 0), ss = make_float4(0, 0, 0, 0);
    for (int r = blockIdx.x * 8 + q; r < NN; r += NB_STATS * 8) {
        uint2 u = Xp[(size_t)r * 32 + c4];
        float2 f01 = __half22float2(*(__half2*)&u.x);
        float2 f23 = __half22float2(*(__half2*)&u.y);
        s.x += f01.x; s.y += f01.y; s.z += f23.x; s.w += f23.y;
        ss.x = fmaf(f01.x, f01.x, ss.x); ss.y = fmaf(f01.y, f01.y, ss.y);
        ss.z = fmaf(f23.x, f23.x, ss.z); ss.w = fmaf(f23.y, f23.y, ss.w);
    }
    red_s[q][c4 * 4 + 0] = s.x; red_s[q][c4 * 4 + 1] = s.y;
    red_s[q][c4 * 4 + 2] = s.z; red_s[q][c4 * 4 + 3] = s.w;
    red_ss[q][c4 * 4 + 0] = ss.x; red_ss[q][c4 * 4 + 1] = ss.y;
    red_ss[q][c4 * 4 + 2] = ss.z; red_ss[q][c4 * 4 + 3] = ss.w;
    __syncthreads();
    if (tid < 128) {
        float ts = 0.f, tss = 0.f;
        #pragma unroll
        for (int k = 0; k < 8; k++) {
            ts += red_s[k][tid];
            tss += red_ss[k][tid];
        }
        g_part[blockIdx.x * (2 * DD) + tid] = ts;
        g_part[blockIdx.x * (2 * DD) + DD + tid] = tss;
    }
}
__global__ __launch_bounds__(256) void k_bnfinish(const float* __restrict__ gamma,
                                                  const float* __restrict__ beta) {
    __shared__ float sh[2][DD];
    int tid = threadIdx.x;
    int c = tid & 127;
    int part = tid >> 7;        // 0 = sum, 1 = sumsq
    float acc = 0.f;
    #pragma unroll 8
    for (int b = 0; b < NB_STATS; b++)
        acc += g_part[b * (2 * DD) + part * DD + c];
    sh[part][c] = acc;
    __syncthreads();
    if (tid < DD) {
        float mean = sh[0][tid] * (1.0f / NN);
        float var = sh[1][tid] * (1.0f / NN) - mean * mean;
        float r = rsqrtf(var + EPSV);
        float sc = r * gamma[tid];
        g_scale[tid] = sc;
        g_shift[tid] = fmaf(-mean, sc, beta[tid]);
    }
}

// ---------------- final: BN2 + residual + leakyrelu (fp32 out) ----------------
__global__ void k_final(const __half* __restrict__ agg, const float* __restrict__ x,
                        float* __restrict__ out) {
    int i = blockIdx.x * blockDim.x + threadIdx.x;   // float4 / uint2 index
    if (i >= NN * DD / 4) return;
    int c = (i & 31) * 4;
    uint2 u = ((const uint2*)agg)[i];
    float2 v01 = __half22float2(*(__half2*)&u.x);
    float2 v23 = __half22float2(*(__half2*)&u.y);
    float4 xr = ((const float4*)x)[i];
    float4 o;
    float y;
    y = fmaf(v01.x, g_scale[c + 0], g_shift[c + 0]) + xr.x; o.x = y > 0.f ? y : NEG * y;
    y = fmaf(v01.y, g_scale[c + 1], g_shift[c + 1]) + xr.y; o.y = y > 0.f ? y : NEG * y;
    y = fmaf(v23.x, g_scale[c + 2], g_shift[c + 2]) + xr.z; o.z = y > 0.f ? y : NEG * y;
    y = fmaf(v23.y, g_scale[c + 3], g_shift[c + 3]) + xr.w; o.w = y > 0.f ? y : NEG * y;
    ((float4*)out)[i] = o;
}

// ---------------- launch ----------------
extern "C" void kernel_launch(void* const* d_in, const int* in_sizes, int n_in,
                              void* d_out, int out_size) {
    const float* x   = (const float*)d_in[0];
    const int*   ei  = (const int*)d_in[1];
    const int*   src = ei;
    const int*   dst = ei + EE;
    const float* W1  = (const float*)d_in[2];
    // b1 = d_in[3]: cancels inside BatchNorm
    const float* g1  = (const float*)d_in[4];
    const float* be1 = (const float*)d_in[5];
    const float* W2  = (const float*)d_in[6];
    // b2 = d_in[7]: cancels likewise
    const float* g2  = (const float*)d_in[8];
    const float* be2 = (const float*)d_in[9];
    float* out = (float*)d_out;

    __half* p_h = nullptr;
    __half* p_buf = nullptr;
    uint2 *p_w1hi, *p_w1lo, *p_w2hi, *p_w2lo;
    cudaGetSymbolAddress((void**)&p_h, g_h);
    cudaGetSymbolAddress((void**)&p_buf, g_buf);
    cudaGetSymbolAddress((void**)&p_w1hi, g_w1hi);
    cudaGetSymbolAddress((void**)&p_w1lo, g_w1lo);
    cudaGetSymbolAddress((void**)&p_w2hi, g_w2hi);
    cudaGetSymbolAddress((void**)&p_w2lo, g_w2lo);

    cudaFuncSetAttribute(k_gemm_l1, cudaFuncAttributeMaxDynamicSharedMemorySize, SMEMG);
    cudaFuncSetAttribute(k_gemm_l2, cudaFuncAttributeMaxDynamicSharedMemorySize, SMEMG);

    // weight prep + graph preprocessing
    k_prepw<<<32, 256>>>(W1, W2);
    k_zero<<<(NN + 255) / 256, 256>>>();
    k_hist<<<(EE / 4 + 255) / 256, 256>>>(dst);
    k_scan1<<<SCAN_BLK, 1024>>>();
    k_scan2<<<1, 128>>>();
    k_scan3<<<SCAN_BLK, 1024>>>();
    k_scatter<<<2048, 256>>>(src, dst);

    // layer 1
    k_gemm_l1<<<(NN + 127) / 128, 256, SMEMG>>>(x, p_w1hi, p_w1lo, p_h);
    k_agg<<<(NN + 7) / 8, 256>>>(p_h, p_buf);
    k_bnstats<<<NB_STATS, 256>>>(p_buf);
    k_bnfinish<<<1, 256>>>(g1, be1);

    // layer 2 (BN1+act fused into GEMM2 A-load)
    k_gemm_l2<<<(NN + 127) / 128, 256, SMEMG>>>(p_buf, p_w2hi, p_w2lo, p_h);
    k_agg<<<(NN + 7) / 8, 256>>>(p_h, p_buf);
    k_bnstats<<<NB_STATS, 256>>>(p_buf);
    k_bnfinish<<<1, 256>>>(g2, be2);
    k_final<<<(NN * DD / 4 + 255) / 256, 256>>>(p_buf, x, out);
}

// round 8
// speedup vs baseline: 2.0207x; 1.0346x over previous
#include <cuda_runtime.h>
#include <cuda_fp16.h>
#include <stdint.h>

#define NN 100000
#define DD 128
#define EE 1600000
#define NEG 0.01f
#define EPSV 1e-5f
#define NB_STATS 512
#define SCAN_BLK 98   // ceil(100000/1024)

// ---------------- device scratch (no allocations allowed) ----------------
__device__ __half g_h[(size_t)NN * DD];    // GEMM output pre-scaled by dinv (h')
__device__ __half g_buf[(size_t)NN * DD];  // aggregation output, fp16
__device__ int   g_cnt[NN];
__device__ int   g_off[NN + 1];            // per-block LOCAL exclusive offsets
__device__ int   g_wpos[NN];               // local write cursors
__device__ int   g_bsum[SCAN_BLK];
__device__ int   g_boff[SCAN_BLK];         // global block offsets
__device__ int   g_ssrc[EE];               // src ids grouped by dst (CSR)
__device__ float g_dinv[NN];
__device__ float g_part[NB_STATS * 2 * DD];
__device__ float g_scale[DD];
__device__ float g_shift[DD];
// W pre-split to fp16 hi/lo as per-thread mma-fragment records
__device__ __align__(16) uint2 g_w1hi[4096];
__device__ __align__(16) uint2 g_w1lo[4096];
__device__ __align__(16) uint2 g_w2hi[4096];
__device__ __align__(16) uint2 g_w2lo[4096];

// ---------------- helpers ----------------
__device__ __forceinline__ uint32_t packh2(__half a, __half b) {
    __half2 t = __halves2half2(a, b);
    return *(uint32_t*)&t;
}
__device__ __forceinline__ void splith2(float x, float y, uint32_t& hi, uint32_t& lo) {
    __half hx = __float2half_rn(x);
    __half hy = __float2half_rn(y);
    float rx = x - __half2float(hx);
    float ry = y - __half2float(hy);
    hi = packh2(hx, hy);
    lo = packh2(__float2half_rn(rx), __float2half_rn(ry));
}
__device__ __forceinline__ void mma16816h(float4& d, const uint32_t a0, const uint32_t a1,
                                          const uint32_t a2, const uint32_t a3,
                                          const uint32_t b0, const uint32_t b1) {
    asm volatile(
        "mma.sync.aligned.m16n8k16.row.col.f32.f16.f16.f32 "
        "{%0,%1,%2,%3}, {%4,%5,%6,%7}, {%8,%9}, {%0,%1,%2,%3};\n"
        : "+f"(d.x), "+f"(d.y), "+f"(d.z), "+f"(d.w)
        : "r"(a0), "r"(a1), "r"(a2), "r"(a3), "r"(b0), "r"(b1));
}

// ---------------- W prep: both matrices in one launch ----------------
__global__ void k_prepw(const float* __restrict__ W1, const float* __restrict__ W2) {
    int i = blockIdx.x * blockDim.x + threadIdx.x;   // 0..8191
    if (i >= 8192) return;
    const float* W = (i < 4096) ? W1 : W2;
    uint2* bhi = (i < 4096) ? g_w1hi : g_w2hi;
    uint2* blo = (i < 4096) ? g_w1lo : g_w2lo;
    int r = i & 4095;
    int lane = r & 31, rec = r >> 5;
    int kb = rec >> 4, nf = rec & 15;
    int g = lane >> 2, tig = lane & 3;
    int k0 = kb * 16 + 2 * tig;
    int n = nf * 8 + g;
    float w00 = W[(k0 + 0) * DD + n];
    float w01 = W[(k0 + 1) * DD + n];
    float w08 = W[(k0 + 8) * DD + n];
    float w09 = W[(k0 + 9) * DD + n];
    uint32_t h0, l0, h1, l1;
    splith2(w00, w01, h0, l0);
    splith2(w08, w09, h1, l1);
    bhi[r] = make_uint2(h0, h1);
    blo[r] = make_uint2(l0, l1);
}

// ---------------- graph preprocessing ----------------
__global__ void k_hist(const int* __restrict__ dst) {
    int i = blockIdx.x * blockDim.x + threadIdx.x;
    if (i < EE / 4) {
        int4 d = ((const int4*)dst)[i];
        atomicAdd(&g_cnt[d.x], 1);
        atomicAdd(&g_cnt[d.y], 1);
        atomicAdd(&g_cnt[d.z], 1);
        atomicAdd(&g_cnt[d.w], 1);
    }
}
// per-block local exclusive scan + dinv + block totals
__global__ __launch_bounds__(1024) void k_scan1() {
    __shared__ int wsum[32];
    int tid = threadIdx.x, lane = tid & 31, wid = tid >> 5;
    int i = blockIdx.x * 1024 + tid;
    int v = (i < NN) ? g_cnt[i] : 0;
    if (i < NN) g_dinv[i] = rsqrtf((float)v + 1.0f);
    int x = v;
    #pragma unroll
    for (int s = 1; s < 32; s <<= 1) {
        int t = __shfl_up_sync(0xFFFFFFFFu, x, s);
        if (lane >= s) x += t;
    }
    if (lane == 31) wsum[wid] = x;
    __syncthreads();
    if (wid == 0) {
        int y = wsum[lane];
        #pragma unroll
        for (int s = 1; s < 32; s <<= 1) {
            int t = __shfl_up_sync(0xFFFFFFFFu, y, s);
            if (lane >= s) y += t;
        }
        wsum[lane] = y;
    }
    __syncthreads();
    int incl = x + (wid > 0 ? wsum[wid - 1] : 0);
    if (i < NN) {
        int excl = incl - v;
        g_off[i] = excl;
        g_wpos[i] = excl;
    }
    if (i == NN - 1) g_off[NN] = incl;   // local inclusive total at the end
    if (tid == 1023) g_bsum[blockIdx.x] = incl;
}
// scan block totals -> g_boff
__global__ void k_scan2() {
    __shared__ int ws[4];
    int tid = threadIdx.x, lane = tid & 31, wid = tid >> 5;
    int v = (tid < SCAN_BLK) ? g_bsum[tid] : 0;
    int x = v;
    #pragma unroll
    for (int s = 1; s < 32; s <<= 1) {
        int t = __shfl_up_sync(0xFFFFFFFFu, x, s);
        if (lane >= s) x += t;
    }
    if (lane == 31) ws[wid] = x;
    __syncthreads();
    int add = 0;
    for (int w = 0; w < wid; w++) add += ws[w];
    int incl = x + add;
    if (tid < SCAN_BLK) g_boff[tid] = incl - v;
}
__global__ void k_scatter(const int* __restrict__ src, const int* __restrict__ dst) {
    for (int e = blockIdx.x * blockDim.x + threadIdx.x; e < EE; e += gridDim.x * blockDim.x) {
        int s = src[e];
        int d = dst[e];
        int p = atomicAdd(&g_wpos[d], 1) + g_boff[d >> 10];
        g_ssrc[p] = s;
    }
}

// ---------------- GEMM layer 1: C = dinv_row * (fp16(A) @ W), fp16 out ----------
#define SMEMG (65536 + 1024)
__global__ __launch_bounds__(256, 2) void k_gemm_l1(const float* __restrict__ A,
                                                    const uint2* __restrict__ Bhi,
                                                    const uint2* __restrict__ Blo,
                                                    __half* __restrict__ C) {
    extern __shared__ unsigned char sm[];
    uint2* sWhi = (uint2*)sm;                     // 32KB
    uint2* sWlo = (uint2*)(sm + 32768);           // 32KB
    const int tid = threadIdx.x;
    #pragma unroll
    for (int i = 0; i < 16; i++) {
        sWhi[tid + i * 256] = Bhi[tid + i * 256];
        sWlo[tid + i * 256] = Blo[tid + i * 256];
    }
    __syncthreads();

    const int w = tid >> 5, lane = tid & 31;
    const int g = lane >> 2, tig = lane & 3;
    const int row0 = blockIdx.x * 128 + w * 16 + g;
    const int row8 = row0 + 8;
    const bool ok0 = row0 < NN, ok8 = row8 < NN;

    float4 acc[16];
    #pragma unroll
    for (int nf = 0; nf < 16; nf++) acc[nf] = make_float4(0.f, 0.f, 0.f, 0.f);

    for (int kb = 0; kb < 8; kb++) {
        const int c0 = kb * 16 + tig * 2;
        const int c1 = c0 + 8;
        float2 v00 = ok0 ? *(const float2*)(A + (size_t)row0 * DD + c0) : make_float2(0.f, 0.f);
        float2 v01 = ok0 ? *(const float2*)(A + (size_t)row0 * DD + c1) : make_float2(0.f, 0.f);
        float2 v10 = ok8 ? *(const float2*)(A + (size_t)row8 * DD + c0) : make_float2(0.f, 0.f);
        float2 v11 = ok8 ? *(const float2*)(A + (size_t)row8 * DD + c1) : make_float2(0.f, 0.f);
        uint32_t a0, a1, a2, a3;
        {
            __half2 t;
            t = __floats2half2_rn(v00.x, v00.y); a0 = *(uint32_t*)&t;
            t = __floats2half2_rn(v10.x, v10.y); a1 = *(uint32_t*)&t;
            t = __floats2half2_rn(v01.x, v01.y); a2 = *(uint32_t*)&t;
            t = __floats2half2_rn(v11.x, v11.y); a3 = *(uint32_t*)&t;
        }
        const uint2* bh = sWhi + (kb * 16) * 32 + lane;
        const uint2* bl = sWlo + (kb * 16) * 32 + lane;
        #pragma unroll
        for (int nf = 0; nf < 16; nf++) {
            uint2 bhv = bh[nf * 32];
            uint2 blv = bl[nf * 32];
            mma16816h(acc[nf], a0, a1, a2, a3, bhv.x, bhv.y);
            mma16816h(acc[nf], a0, a1, a2, a3, blv.x, blv.y);
        }
    }
    const float di0 = ok0 ? g_dinv[row0] : 0.f;
    const float di8 = ok8 ? g_dinv[row8] : 0.f;
    if (ok0) {
        #pragma unroll
        for (int nf = 0; nf < 16; nf++) {
            __half2 o = __floats2half2_rn(acc[nf].x * di0, acc[nf].y * di0);
            *(__half2*)(C + (size_t)row0 * DD + nf * 8 + tig * 2) = o;
        }
    }
    if (ok8) {
        #pragma unroll
        for (int nf = 0; nf < 16; nf++) {
            __half2 o = __floats2half2_rn(acc[nf].z * di8, acc[nf].w * di8);
            *(__half2*)(C + (size_t)row8 * DD + nf * 8 + tig * 2) = o;
        }
    }
}

// ---------------- GEMM layer 2: A fp16 + BN1+leakyrelu fused, dinv-scaled out ----
__global__ __launch_bounds__(256, 2) void k_gemm_l2(const __half* __restrict__ A,
                                                    const uint2* __restrict__ Bhi,
                                                    const uint2* __restrict__ Blo,
                                                    __half* __restrict__ C) {
    extern __shared__ unsigned char sm[];
    uint2* sWhi = (uint2*)sm;
    uint2* sWlo = (uint2*)(sm + 32768);
    float* sSc = (float*)(sm + 65536);
    float* sSh = (float*)(sm + 66048);
    const int tid = threadIdx.x;
    #pragma unroll
    for (int i = 0; i < 16; i++) {
        sWhi[tid + i * 256] = Bhi[tid + i * 256];
        sWlo[tid + i * 256] = Blo[tid + i * 256];
    }
    if (tid < 128) {
        sSc[tid] = g_scale[tid];
        sSh[tid] = g_shift[tid];
    }
    __syncthreads();

    const int w = tid >> 5, lane = tid & 31;
    const int g = lane >> 2, tig = lane & 3;
    const int row0 = blockIdx.x * 128 + w * 16 + g;
    const int row8 = row0 + 8;
    const bool ok0 = row0 < NN, ok8 = row8 < NN;
    const uint32_t* __restrict__ Ah2 = (const uint32_t*)A;   // half2 view

    float4 acc[16];
    #pragma unroll
    for (int nf = 0; nf < 16; nf++) acc[nf] = make_float4(0.f, 0.f, 0.f, 0.f);

    for (int kb = 0; kb < 8; kb++) {
        const int c0 = kb * 16 + tig * 2;
        const int c1 = c0 + 8;
        uint32_t r00 = ok0 ? Ah2[(size_t)row0 * 64 + (c0 >> 1)] : 0u;
        uint32_t r01 = ok0 ? Ah2[(size_t)row0 * 64 + (c1 >> 1)] : 0u;
        uint32_t r10 = ok8 ? Ah2[(size_t)row8 * 64 + (c0 >> 1)] : 0u;
        uint32_t r11 = ok8 ? Ah2[(size_t)row8 * 64 + (c1 >> 1)] : 0u;
        float2 sc0 = *(const float2*)&sSc[c0], sh0 = *(const float2*)&sSh[c0];
        float2 sc1 = *(const float2*)&sSc[c1], sh1 = *(const float2*)&sSh[c1];
        uint32_t a0, a1, a2, a3;
        {
            float2 f; float y0, y1; __half2 t;
            f = __half22float2(*(__half2*)&r00);
            y0 = fmaf(f.x, sc0.x, sh0.x); y0 = y0 > 0.f ? y0 : NEG * y0;
            y1 = fmaf(f.y, sc0.y, sh0.y); y1 = y1 > 0.f ? y1 : NEG * y1;
            t = __floats2half2_rn(y0, y1); a0 = *(uint32_t*)&t;
            f = __half22float2(*(__half2*)&r10);
            y0 = fmaf(f.x, sc0.x, sh0.x); y0 = y0 > 0.f ? y0 : NEG * y0;
            y1 = fmaf(f.y, sc0.y, sh0.y); y1 = y1 > 0.f ? y1 : NEG * y1;
            t = __floats2half2_rn(y0, y1); a1 = *(uint32_t*)&t;
            f = __half22float2(*(__half2*)&r01);
            y0 = fmaf(f.x, sc1.x, sh1.x); y0 = y0 > 0.f ? y0 : NEG * y0;
            y1 = fmaf(f.y, sc1.y, sh1.y); y1 = y1 > 0.f ? y1 : NEG * y1;
            t = __floats2half2_rn(y0, y1); a2 = *(uint32_t*)&t;
            f = __half22float2(*(__half2*)&r11);
            y0 = fmaf(f.x, sc1.x, sh1.x); y0 = y0 > 0.f ? y0 : NEG * y0;
            y1 = fmaf(f.y, sc1.y, sh1.y); y1 = y1 > 0.f ? y1 : NEG * y1;
            t = __floats2half2_rn(y0, y1); a3 = *(uint32_t*)&t;
        }
        const uint2* bh = sWhi + (kb * 16) * 32 + lane;
        const uint2* bl = sWlo + (kb * 16) * 32 + lane;
        #pragma unroll
        for (int nf = 0; nf < 16; nf++) {
            uint2 bhv = bh[nf * 32];
            uint2 blv = bl[nf * 32];
            mma16816h(acc[nf], a0, a1, a2, a3, bhv.x, bhv.y);
            mma16816h(acc[nf], a0, a1, a2, a3, blv.x, blv.y);
        }
    }
    const float di0 = ok0 ? g_dinv[row0] : 0.f;
    const float di8 = ok8 ? g_dinv[row8] : 0.f;
    if (ok0) {
        #pragma unroll
        for (int nf = 0; nf < 16; nf++) {
            __half2 o = __floats2half2_rn(acc[nf].x * di0, acc[nf].y * di0);
            *(__half2*)(C + (size_t)row0 * DD + nf * 8 + tig * 2) = o;
        }
    }
    if (ok8) {
        #pragma unroll
        for (int nf = 0; nf < 16; nf++) {
            __half2 o = __floats2half2_rn(acc[nf].z * di8, acc[nf].w * di8);
            *(__half2*)(C + (size_t)row8 * DD + nf * 8 + tig * 2) = o;
        }
    }
}

// ---------------- per-node CSR aggregation (one warp per dst node) --------
// h is pre-scaled by dinv -> weightless gather+add; coalesced edge index loads.
__global__ void k_agg(const __half* __restrict__ h, __half* __restrict__ agg) {
    int warp = (blockIdx.x * blockDim.x + threadIdx.x) >> 5;
    int lane = threadIdx.x & 31;
    if (warp >= NN) return;
    const uint2* __restrict__ hp = (const uint2*)h;   // 4 halves per lane
    float di = g_dinv[warp];
    uint2 sv = hp[(size_t)warp * 32 + lane];          // self (already dinv-scaled)
    float2 a01 = __half22float2(*(__half2*)&sv.x);
    float2 a23 = __half22float2(*(__half2*)&sv.y);
    float4 acc = make_float4(a01.x, a01.y, a23.x, a23.y);
    int e0 = g_off[warp] + g_boff[warp >> 10];
    int e1 = g_off[warp + 1] + g_boff[(warp + 1) >> 10];
    for (int base = e0; base < e1; base += 32) {
        int t = base + lane;
        int idx = (t < e1) ? g_ssrc[t] : 0;           // one coalesced LDG per 32 edges
        int cnt = min(32, e1 - base);
        int j = 0;
        for (; j + 8 <= cnt; j += 8) {
            int s0 = __shfl_sync(0xFFFFFFFFu, idx, j);
            int s1 = __shfl_sync(0xFFFFFFFFu, idx, j + 1);
            int s2 = __shfl_sync(0xFFFFFFFFu, idx, j + 2);
            int s3 = __shfl_sync(0xFFFFFFFFu, idx, j + 3);
            int s4 = __shfl_sync(0xFFFFFFFFu, idx, j + 4);
            int s5 = __shfl_sync(0xFFFFFFFFu, idx, j + 5);
            int s6 = __shfl_sync(0xFFFFFFFFu, idx, j + 6);
            int s7 = __shfl_sync(0xFFFFFFFFu, idx, j + 7);
            uint2 v0 = hp[(size_t)s0 * 32 + lane];
            uint2 v1 = hp[(size_t)s1 * 32 + lane];
            uint2 v2 = hp[(size_t)s2 * 32 + lane];
            uint2 v3 = hp[(size_t)s3 * 32 + lane];
            uint2 v4 = hp[(size_t)s4 * 32 + lane];
            uint2 v5 = hp[(size_t)s5 * 32 + lane];
            uint2 v6 = hp[(size_t)s6 * 32 + lane];
            uint2 v7 = hp[(size_t)s7 * 32 + lane];
            float2 f;
            f = __half22float2(*(__half2*)&v0.x); acc.x += f.x; acc.y += f.y;
            f = __half22float2(*(__half2*)&v0.y); acc.z += f.x; acc.w += f.y;
            f = __half22float2(*(__half2*)&v1.x); acc.x += f.x; acc.y += f.y;
            f = __half22float2(*(__half2*)&v1.y); acc.z += f.x; acc.w += f.y;
            f = __half22float2(*(__half2*)&v2.x); acc.x += f.x; acc.y += f.y;
            f = __half22float2(*(__half2*)&v2.y); acc.z += f.x; acc.w += f.y;
            f = __half22float2(*(__half2*)&v3.x); acc.x += f.x; acc.y += f.y;
            f = __half22float2(*(__half2*)&v3.y); acc.z += f.x; acc.w += f.y;
            f = __half22float2(*(__half2*)&v4.x); acc.x += f.x; acc.y += f.y;
            f = __half22float2(*(__half2*)&v4.y); acc.z += f.x; acc.w += f.y;
            f = __half22float2(*(__half2*)&v5.x); acc.x += f.x; acc.y += f.y;
            f = __half22float2(*(__half2*)&v5.y); acc.z += f.x; acc.w += f.y;
            f = __half22float2(*(__half2*)&v6.x); acc.x += f.x; acc.y += f.y;
            f = __half22float2(*(__half2*)&v6.y); acc.z += f.x; acc.w += f.y;
            f = __half22float2(*(__half2*)&v7.x); acc.x += f.x; acc.y += f.y;
            f = __half22float2(*(__half2*)&v7.y); acc.z += f.x; acc.w += f.y;
        }
        for (; j < cnt; j++) {
            int s = __shfl_sync(0xFFFFFFFFu, idx, j);
            uint2 v = hp[(size_t)s * 32 + lane];
            float2 f;
            f = __half22float2(*(__half2*)&v.x); acc.x += f.x; acc.y += f.y;
            f = __half22float2(*(__half2*)&v.y); acc.z += f.x; acc.w += f.y;
        }
    }
    acc.x *= di; acc.y *= di; acc.z *= di; acc.w *= di;
    __half2 o01 = __floats2half2_rn(acc.x, acc.y);
    __half2 o23 = __floats2half2_rn(acc.z, acc.w);
    ((uint2*)agg)[(size_t)warp * 32 + lane] = make_uint2(*(uint32_t*)&o01, *(uint32_t*)&o23);
}

// ---------------- batch norm statistics (fp16 input, fp32 sums) ----------------
__global__ __launch_bounds__(256) void k_bnstats(const __half* __restrict__ X) {
    __shared__ float red_s[8][DD];
    __shared__ float red_ss[8][DD];
    int tid = threadIdx.x;
    int c4 = tid & 31;
    int q = tid >> 5;
    const uint2* Xp = (const uint2*)X;
    float4 s = make_float4(0, 0, 0, 0), ss = make_float4(0, 0, 0, 0);
    for (int r = blockIdx.x * 8 + q; r < NN; r += NB_STATS * 8) {
        uint2 u = Xp[(size_t)r * 32 + c4];
        float2 f01 = __half22float2(*(__half2*)&u.x);
        float2 f23 = __half22float2(*(__half2*)&u.y);
        s.x += f01.x; s.y += f01.y; s.z += f23.x; s.w += f23.y;
        ss.x = fmaf(f01.x, f01.x, ss.x); ss.y = fmaf(f01.y, f01.y, ss.y);
        ss.z = fmaf(f23.x, f23.x, ss.z); ss.w = fmaf(f23.y, f23.y, ss.w);
    }
    red_s[q][c4 * 4 + 0] = s.x; red_s[q][c4 * 4 + 1] = s.y;
    red_s[q][c4 * 4 + 2] = s.z; red_s[q][c4 * 4 + 3] = s.w;
    red_ss[q][c4 * 4 + 0] = ss.x; red_ss[q][c4 * 4 + 1] = ss.y;
    red_ss[q][c4 * 4 + 2] = ss.z; red_ss[q][c4 * 4 + 3] = ss.w;
    __syncthreads();
    if (tid < 128) {
        float ts = 0.f, tss = 0.f;
        #pragma unroll
        for (int k = 0; k < 8; k++) {
            ts += red_s[k][tid];
            tss += red_ss[k][tid];
        }
        g_part[blockIdx.x * (2 * DD) + tid] = ts;
        g_part[blockIdx.x * (2 * DD) + DD + tid] = tss;
    }
}
__global__ __launch_bounds__(256) void k_bnfinish(const float* __restrict__ gamma,
                                                  const float* __restrict__ beta) {
    __shared__ float sh[2][DD];
    int tid = threadIdx.x;
    int c = tid & 127;
    int part = tid >> 7;        // 0 = sum, 1 = sumsq
    float acc = 0.f;
    #pragma unroll 8
    for (int b = 0; b < NB_STATS; b++)
        acc += g_part[b * (2 * DD) + part * DD + c];
    sh[part][c] = acc;
    __syncthreads();
    if (tid < DD) {
        float mean = sh[0][tid] * (1.0f / NN);
        float var = sh[1][tid] * (1.0f / NN) - mean * mean;
        float r = rsqrtf(var + EPSV);
        float sc = r * gamma[tid];
        g_scale[tid] = sc;
        g_shift[tid] = fmaf(-mean, sc, beta[tid]);
    }
}

// ---------------- final: BN2 + residual + leakyrelu (fp32 out) ----------------
__global__ void k_final(const __half* __restrict__ agg, const float* __restrict__ x,
                        float* __restrict__ out) {
    int i = blockIdx.x * blockDim.x + threadIdx.x;
    if (i >= NN * DD / 4) return;
    int c = (i & 31) * 4;
    uint2 u = ((const uint2*)agg)[i];
    float2 v01 = __half22float2(*(__half2*)&u.x);
    float2 v23 = __half22float2(*(__half2*)&u.y);
    float4 xr = ((const float4*)x)[i];
    float4 o;
    float y;
    y = fmaf(v01.x, g_scale[c + 0], g_shift[c + 0]) + xr.x; o.x = y > 0.f ? y : NEG * y;
    y = fmaf(v01.y, g_scale[c + 1], g_shift[c + 1]) + xr.y; o.y = y > 0.f ? y : NEG * y;
    y = fmaf(v23.x, g_scale[c + 2], g_shift[c + 2]) + xr.z; o.z = y > 0.f ? y : NEG * y;
    y = fmaf(v23.y, g_scale[c + 3], g_shift[c + 3]) + xr.w; o.w = y > 0.f ? y : NEG * y;
    ((float4*)out)[i] = o;
}

// ---------------- launch ----------------
extern "C" void kernel_launch(void* const* d_in, const int* in_sizes, int n_in,
                              void* d_out, int out_size) {
    const float* x   = (const float*)d_in[0];
    const int*   ei  = (const int*)d_in[1];
    const int*   src = ei;
    const int*   dst = ei + EE;
    const float* W1  = (const float*)d_in[2];
    // b1 = d_in[3]: cancels inside BatchNorm
    const float* g1  = (const float*)d_in[4];
    const float* be1 = (const float*)d_in[5];
    const float* W2  = (const float*)d_in[6];
    // b2 = d_in[7]: cancels likewise
    const float* g2  = (const float*)d_in[8];
    const float* be2 = (const float*)d_in[9];
    float* out = (float*)d_out;

    __half* p_h = nullptr;
    __half* p_buf = nullptr;
    int* p_cnt = nullptr;
    uint2 *p_w1hi, *p_w1lo, *p_w2hi, *p_w2lo;
    cudaGetSymbolAddress((void**)&p_h, g_h);
    cudaGetSymbolAddress((void**)&p_buf, g_buf);
    cudaGetSymbolAddress((void**)&p_cnt, g_cnt);
    cudaGetSymbolAddress((void**)&p_w1hi, g_w1hi);
    cudaGetSymbolAddress((void**)&p_w1lo, g_w1lo);
    cudaGetSymbolAddress((void**)&p_w2hi, g_w2hi);
    cudaGetSymbolAddress((void**)&p_w2lo, g_w2lo);

    cudaFuncSetAttribute(k_gemm_l1, cudaFuncAttributeMaxDynamicSharedMemorySize, SMEMG);
    cudaFuncSetAttribute(k_gemm_l2, cudaFuncAttributeMaxDynamicSharedMemorySize, SMEMG);

    // second stream + events for fork-join (created per call; host-side only,
    // not replayed by the graph). Fall back to single-stream on any failure.
    cudaStream_t s2 = 0;
    bool forked = (cudaStreamCreateWithFlags(&s2, cudaStreamNonBlocking) == cudaSuccess);
    cudaEvent_t eFork = 0, eDinv = 0, eGemm = 0;
    if (forked) forked = (cudaEventCreateWithFlags(&eFork, cudaEventDisableTiming) == cudaSuccess);
    if (forked) forked = (cudaEventCreateWithFlags(&eDinv, cudaEventDisableTiming) == cudaSuccess);
    if (forked) forked = (cudaEventCreateWithFlags(&eGemm, cudaEventDisableTiming) == cudaSuccess);
    cudaStream_t sG = forked ? s2 : (cudaStream_t)0;

    // default stream: edge preprocessing. s2: weight prep + GEMM1 (needs dinv).
    cudaMemsetAsync(p_cnt, 0, NN * sizeof(int), 0);
    if (forked) {
        cudaEventRecord(eFork, 0);
        cudaStreamWaitEvent(s2, eFork, 0);
    }
    k_prepw<<<32, 256, 0, sG>>>(W1, W2);
    k_hist<<<(EE / 4 + 255) / 256, 256>>>(dst);
    k_scan1<<<SCAN_BLK, 1024>>>();
    if (forked) {
        cudaEventRecord(eDinv, 0);
        cudaStreamWaitEvent(s2, eDinv, 0);
    }
    k_scan2<<<1, 128>>>();
    k_scatter<<<2048, 256>>>(src, dst);
    k_gemm_l1<<<(NN + 127) / 128, 256, SMEMG, sG>>>(x, p_w1hi, p_w1lo, p_h);
    if (forked) {
        cudaEventRecord(eGemm, s2);
        cudaStreamWaitEvent(0, eGemm, 0);   // join: agg needs scatter AND gemm1
    }

    // layer 1 (rest on default stream)
    k_agg<<<(NN + 7) / 8, 256>>>(p_h, p_buf);
    k_bnstats<<<NB_STATS, 256>>>(p_buf);
    k_bnfinish<<<1, 256>>>(g1, be1);

    // layer 2 (BN1+act fused into GEMM2 A-load)
    k_gemm_l2<<<(NN + 127) / 128, 256, SMEMG>>>(p_buf, p_w2hi, p_w2lo, p_h);
    k_agg<<<(NN + 7) / 8, 256>>>(p_h, p_buf);
    k_bnstats<<<NB_STATS, 256>>>(p_buf);
    k_bnfinish<<<1, 256>>>(g2, be2);
    k_final<<<(NN * DD / 4 + 255) / 256, 256>>>(p_buf, x, out);
}

// round 9
// speedup vs baseline: 2.2504x; 1.1137x over previous
#include <cuda_runtime.h>
#include <cuda_fp16.h>
#include <stdint.h>

#define NN 100000
#define DD 128
#define EE 1600000
#define NEG 0.01f
#define EPSV 1e-5f
#define SCAN_BLK 98   // ceil(100000/1024)

// ---------------- device scratch (no allocations allowed) ----------------
__device__ __half g_h[(size_t)NN * DD];    // GEMM output pre-scaled by dinv (h')
__device__ __half g_buf[(size_t)NN * DD];  // aggregation output, fp16
__device__ int   g_cnt[NN];
__device__ int   g_off[NN + 1];            // per-block LOCAL exclusive offsets
__device__ int   g_wpos[NN];               // local write cursors
__device__ int   g_bsum[SCAN_BLK];
__device__ int   g_boff[SCAN_BLK];         // global block offsets
__device__ int   g_ssrc[EE];               // src ids grouped by dst (CSR)
__device__ float g_dinv[NN];
__device__ float g_stats[4][8][DD];        // [0]=s1 [1]=ss1 [2]=s2 [3]=ss2, 8 buckets
__device__ int   g_ctr;                    // scan1 last-block ticket
// W pre-split to fp16 hi/lo as per-thread mma-fragment records
__device__ __align__(16) uint2 g_w1hi[4096];
__device__ __align__(16) uint2 g_w1lo[4096];
__device__ __align__(16) uint2 g_w2hi[4096];
__device__ __align__(16) uint2 g_w2lo[4096];

// ---------------- helpers ----------------
__device__ __forceinline__ uint32_t packh2(__half a, __half b) {
    __half2 t = __halves2half2(a, b);
    return *(uint32_t*)&t;
}
__device__ __forceinline__ void splith2(float x, float y, uint32_t& hi, uint32_t& lo) {
    __half hx = __float2half_rn(x);
    __half hy = __float2half_rn(y);
    float rx = x - __half2float(hx);
    float ry = y - __half2float(hy);
    hi = packh2(hx, hy);
    lo = packh2(__float2half_rn(rx), __float2half_rn(ry));
}
__device__ __forceinline__ void mma16816h(float4& d, const uint32_t a0, const uint32_t a1,
                                          const uint32_t a2, const uint32_t a3,
                                          const uint32_t b0, const uint32_t b1) {
    asm volatile(
        "mma.sync.aligned.m16n8k16.row.col.f32.f16.f16.f32 "
        "{%0,%1,%2,%3}, {%4,%5,%6,%7}, {%8,%9}, {%0,%1,%2,%3};\n"
        : "+f"(d.x), "+f"(d.y), "+f"(d.z), "+f"(d.w)
        : "r"(a0), "r"(a1), "r"(a2), "r"(a3), "r"(b0), "r"(b1));
}

// ---------------- W prep: both matrices in one launch ----------------
__global__ void k_prepw(const float* __restrict__ W1, const float* __restrict__ W2) {
    int i = blockIdx.x * blockDim.x + threadIdx.x;   // 0..8191
    if (i >= 8192) return;
    const float* W = (i < 4096) ? W1 : W2;
    uint2* bhi = (i < 4096) ? g_w1hi : g_w2hi;
    uint2* blo = (i < 4096) ? g_w1lo : g_w2lo;
    int r = i & 4095;
    int lane = r & 31, rec = r >> 5;
    int kb = rec >> 4, nf = rec & 15;
    int g = lane >> 2, tig = lane & 3;
    int k0 = kb * 16 + 2 * tig;
    int n = nf * 8 + g;
    float w00 = W[(k0 + 0) * DD + n];
    float w01 = W[(k0 + 1) * DD + n];
    float w08 = W[(k0 + 8) * DD + n];
    float w09 = W[(k0 + 9) * DD + n];
    uint32_t h0, l0, h1, l1;
    splith2(w00, w01, h0, l0);
    splith2(w08, w09, h1, l1);
    bhi[r] = make_uint2(h0, h1);
    blo[r] = make_uint2(l0, l1);
}

// ---------------- graph preprocessing ----------------
__global__ void k_hist(const int* __restrict__ dst) {
    int i = blockIdx.x * blockDim.x + threadIdx.x;
    if (i < EE / 4) {
        int4 d = ((const int4*)dst)[i];
        atomicAdd(&g_cnt[d.x], 1);
        atomicAdd(&g_cnt[d.y], 1);
        atomicAdd(&g_cnt[d.z], 1);
        atomicAdd(&g_cnt[d.w], 1);
    }
}
// per-block local exclusive scan + dinv + block totals; last block scans totals
__global__ __launch_bounds__(1024) void k_scan1() {
    __shared__ int wsum[32];
    __shared__ int lastblk;
    int tid = threadIdx.x, lane = tid & 31, wid = tid >> 5;
    int i = blockIdx.x * 1024 + tid;
    int v = (i < NN) ? g_cnt[i] : 0;
    if (i < NN) g_dinv[i] = rsqrtf((float)v + 1.0f);
    int x = v;
    #pragma unroll
    for (int s = 1; s < 32; s <<= 1) {
        int t = __shfl_up_sync(0xFFFFFFFFu, x, s);
        if (lane >= s) x += t;
    }
    if (lane == 31) wsum[wid] = x;
    __syncthreads();
    if (wid == 0) {
        int y = wsum[lane];
        #pragma unroll
        for (int s = 1; s < 32; s <<= 1) {
            int t = __shfl_up_sync(0xFFFFFFFFu, y, s);
            if (lane >= s) y += t;
        }
        wsum[lane] = y;
    }
    __syncthreads();
    int incl = x + (wid > 0 ? wsum[wid - 1] : 0);
    if (i < NN) {
        int excl = incl - v;
        g_off[i] = excl;
        g_wpos[i] = excl;
    }
    if (i == NN - 1) g_off[NN] = incl;   // local inclusive total at the end
    if (tid == 1023) g_bsum[blockIdx.x] = incl;
    // last-block ticket: scan the 98 block totals in this kernel
    __threadfence();
    __syncthreads();
    if (tid == 0) lastblk = (atomicAdd(&g_ctr, 1) == SCAN_BLK - 1) ? 1 : 0;
    __syncthreads();
    if (lastblk && wid == 0) {
        int bv = (lane < 32 && lane < SCAN_BLK) ? g_bsum[lane] : 0;
        // 98 entries: process in 4 chunks of 32 with carried base (warp 0 only)
        int carry = 0;
        for (int base = 0; base < SCAN_BLK; base += 32) {
            int idx2 = base + lane;
            int vv = (idx2 < SCAN_BLK) ? g_bsum[idx2] : 0;
            int xx = vv;
            #pragma unroll
            for (int s = 1; s < 32; s <<= 1) {
                int t = __shfl_up_sync(0xFFFFFFFFu, xx, s);
                if (lane >= s) xx += t;
            }
            if (idx2 < SCAN_BLK) g_boff[idx2] = xx - vv + carry;
            carry += __shfl_sync(0xFFFFFFFFu, xx, 31);
        }
        (void)bv;
    }
}
__global__ void k_scatter(const int* __restrict__ src, const int* __restrict__ dst) {
    for (int e = blockIdx.x * blockDim.x + threadIdx.x; e < EE; e += gridDim.x * blockDim.x) {
        int s = src[e];
        int d = dst[e];
        int p = atomicAdd(&g_wpos[d], 1) + g_boff[d >> 10];
        g_ssrc[p] = s;
    }
}

// ---------------- GEMM layer 1: C = dinv_row * (fp16(A) @ W), fp16 out ----------
#define SMEMG (65536 + 1024)
__global__ __launch_bounds__(256, 2) void k_gemm_l1(const float* __restrict__ A,
                                                    const uint2* __restrict__ Bhi,
                                                    const uint2* __restrict__ Blo,
                                                    __half* __restrict__ C) {
    extern __shared__ unsigned char sm[];
    uint2* sWhi = (uint2*)sm;                     // 32KB
    uint2* sWlo = (uint2*)(sm + 32768);           // 32KB
    const int tid = threadIdx.x;
    #pragma unroll
    for (int i = 0; i < 16; i++) {
        sWhi[tid + i * 256] = Bhi[tid + i * 256];
        sWlo[tid + i * 256] = Blo[tid + i * 256];
    }
    __syncthreads();

    const int w = tid >> 5, lane = tid & 31;
    const int g = lane >> 2, tig = lane & 3;
    const int row0 = blockIdx.x * 128 + w * 16 + g;
    const int row8 = row0 + 8;
    const bool ok0 = row0 < NN, ok8 = row8 < NN;

    float4 acc[16];
    #pragma unroll
    for (int nf = 0; nf < 16; nf++) acc[nf] = make_float4(0.f, 0.f, 0.f, 0.f);

    for (int kb = 0; kb < 8; kb++) {
        const int c0 = kb * 16 + tig * 2;
        const int c1 = c0 + 8;
        float2 v00 = ok0 ? *(const float2*)(A + (size_t)row0 * DD + c0) : make_float2(0.f, 0.f);
        float2 v01 = ok0 ? *(const float2*)(A + (size_t)row0 * DD + c1) : make_float2(0.f, 0.f);
        float2 v10 = ok8 ? *(const float2*)(A + (size_t)row8 * DD + c0) : make_float2(0.f, 0.f);
        float2 v11 = ok8 ? *(const float2*)(A + (size_t)row8 * DD + c1) : make_float2(0.f, 0.f);
        uint32_t a0, a1, a2, a3;
        {
            __half2 t;
            t = __floats2half2_rn(v00.x, v00.y); a0 = *(uint32_t*)&t;
            t = __floats2half2_rn(v10.x, v10.y); a1 = *(uint32_t*)&t;
            t = __floats2half2_rn(v01.x, v01.y); a2 = *(uint32_t*)&t;
            t = __floats2half2_rn(v11.x, v11.y); a3 = *(uint32_t*)&t;
        }
        const uint2* bh = sWhi + (kb * 16) * 32 + lane;
        const uint2* bl = sWlo + (kb * 16) * 32 + lane;
        #pragma unroll
        for (int nf = 0; nf < 16; nf++) {
            uint2 bhv = bh[nf * 32];
            uint2 blv = bl[nf * 32];
            mma16816h(acc[nf], a0, a1, a2, a3, bhv.x, bhv.y);
            mma16816h(acc[nf], a0, a1, a2, a3, blv.x, blv.y);
        }
    }
    const float di0 = ok0 ? g_dinv[row0] : 0.f;
    const float di8 = ok8 ? g_dinv[row8] : 0.f;
    if (ok0) {
        #pragma unroll
        for (int nf = 0; nf < 16; nf++) {
            __half2 o = __floats2half2_rn(acc[nf].x * di0, acc[nf].y * di0);
            *(__half2*)(C + (size_t)row0 * DD + nf * 8 + tig * 2) = o;
        }
    }
    if (ok8) {
        #pragma unroll
        for (int nf = 0; nf < 16; nf++) {
            __half2 o = __floats2half2_rn(acc[nf].z * di8, acc[nf].w * di8);
            *(__half2*)(C + (size_t)row8 * DD + nf * 8 + tig * 2) = o;
        }
    }
}

// ---------------- GEMM layer 2: A fp16, BN1 (from fused stats) + leakyrelu -------
__global__ __launch_bounds__(256, 2) void k_gemm_l2(const __half* __restrict__ A,
                                                    const uint2* __restrict__ Bhi,
                                                    const uint2* __restrict__ Blo,
                                                    __half* __restrict__ C,
                                                    const float* __restrict__ gamma,
                                                    const float* __restrict__ beta) {
    extern __shared__ unsigned char sm[];
    uint2* sWhi = (uint2*)sm;
    uint2* sWlo = (uint2*)(sm + 32768);
    float* sSc = (float*)(sm + 65536);
    float* sSh = (float*)(sm + 66048);
    const int tid = threadIdx.x;
    #pragma unroll
    for (int i = 0; i < 16; i++) {
        sWhi[tid + i * 256] = Bhi[tid + i * 256];
        sWlo[tid + i * 256] = Blo[tid + i * 256];
    }
    if (tid < 128) {
        float s = 0.f, ss = 0.f;
        #pragma unroll
        for (int b = 0; b < 8; b++) {
            s += g_stats[0][b][tid];
            ss += g_stats[1][b][tid];
        }
        float mean = s * (1.0f / NN);
        float var = ss * (1.0f / NN) - mean * mean;
        float r = rsqrtf(var + EPSV);
        float sc = r * gamma[tid];
        sSc[tid] = sc;
        sSh[tid] = fmaf(-mean, sc, beta[tid]);
    }
    __syncthreads();

    const int w = tid >> 5, lane = tid & 31;
    const int g = lane >> 2, tig = lane & 3;
    const int row0 = blockIdx.x * 128 + w * 16 + g;
    const int row8 = row0 + 8;
    const bool ok0 = row0 < NN, ok8 = row8 < NN;
    const uint32_t* __restrict__ Ah2 = (const uint32_t*)A;   // half2 view

    float4 acc[16];
    #pragma unroll
    for (int nf = 0; nf < 16; nf++) acc[nf] = make_float4(0.f, 0.f, 0.f, 0.f);

    for (int kb = 0; kb < 8; kb++) {
        const int c0 = kb * 16 + tig * 2;
        const int c1 = c0 + 8;
        uint32_t r00 = ok0 ? Ah2[(size_t)row0 * 64 + (c0 >> 1)] : 0u;
        uint32_t r01 = ok0 ? Ah2[(size_t)row0 * 64 + (c1 >> 1)] : 0u;
        uint32_t r10 = ok8 ? Ah2[(size_t)row8 * 64 + (c0 >> 1)] : 0u;
        uint32_t r11 = ok8 ? Ah2[(size_t)row8 * 64 + (c1 >> 1)] : 0u;
        float2 sc0 = *(const float2*)&sSc[c0], sh0 = *(const float2*)&sSh[c0];
        float2 sc1 = *(const float2*)&sSc[c1], sh1 = *(const float2*)&sSh[c1];
        uint32_t a0, a1, a2, a3;
        {
            float2 f; float y0, y1; __half2 t;
            f = __half22float2(*(__half2*)&r00);
            y0 = fmaf(f.x, sc0.x, sh0.x); y0 = y0 > 0.f ? y0 : NEG * y0;
            y1 = fmaf(f.y, sc0.y, sh0.y); y1 = y1 > 0.f ? y1 : NEG * y1;
            t = __floats2half2_rn(y0, y1); a0 = *(uint32_t*)&t;
            f = __half22float2(*(__half2*)&r10);
            y0 = fmaf(f.x, sc0.x, sh0.x); y0 = y0 > 0.f ? y0 : NEG * y0;
            y1 = fmaf(f.y, sc0.y, sh0.y); y1 = y1 > 0.f ? y1 : NEG * y1;
            t = __floats2half2_rn(y0, y1); a1 = *(uint32_t*)&t;
            f = __half22float2(*(__half2*)&r01);
            y0 = fmaf(f.x, sc1.x, sh1.x); y0 = y0 > 0.f ? y0 : NEG * y0;
            y1 = fmaf(f.y, sc1.y, sh1.y); y1 = y1 > 0.f ? y1 : NEG * y1;
            t = __floats2half2_rn(y0, y1); a2 = *(uint32_t*)&t;
            f = __half22float2(*(__half2*)&r11);
            y0 = fmaf(f.x, sc1.x, sh1.x); y0 = y0 > 0.f ? y0 : NEG * y0;
            y1 = fmaf(f.y, sc1.y, sh1.y); y1 = y1 > 0.f ? y1 : NEG * y1;
            t = __floats2half2_rn(y0, y1); a3 = *(uint32_t*)&t;
        }
        const uint2* bh = sWhi + (kb * 16) * 32 + lane;
        const uint2* bl = sWlo + (kb * 16) * 32 + lane;
        #pragma unroll
        for (int nf = 0; nf < 16; nf++) {
            uint2 bhv = bh[nf * 32];
            uint2 blv = bl[nf * 32];
            mma16816h(acc[nf], a0, a1, a2, a3, bhv.x, bhv.y);
            mma16816h(acc[nf], a0, a1, a2, a3, blv.x, blv.y);
        }
    }
    const float di0 = ok0 ? g_dinv[row0] : 0.f;
    const float di8 = ok8 ? g_dinv[row8] : 0.f;
    if (ok0) {
        #pragma unroll
        for (int nf = 0; nf < 16; nf++) {
            __half2 o = __floats2half2_rn(acc[nf].x * di0, acc[nf].y * di0);
            *(__half2*)(C + (size_t)row0 * DD + nf * 8 + tig * 2) = o;
        }
    }
    if (ok8) {
        #pragma unroll
        for (int nf = 0; nf < 16; nf++) {
            __half2 o = __floats2half2_rn(acc[nf].z * di8, acc[nf].w * di8);
            *(__half2*)(C + (size_t)row8 * DD + nf * 8 + tig * 2) = o;
        }
    }
}

// ---------------- per-node CSR aggregation + fused BN stats --------------
// h pre-scaled by dinv -> weightless gather+add. Grid = exactly NN/8 blocks.
// layer selects stats buckets: g_stats[2*layer], g_stats[2*layer+1].
__global__ __launch_bounds__(256) void k_agg(const __half* __restrict__ h,
                                             __half* __restrict__ agg, int layer) {
    __shared__ float rs[8][DD];
    __shared__ float rss[8][DD];
    int node = blockIdx.x * 8 + (threadIdx.x >> 5);
    int q = threadIdx.x >> 5;
    int lane = threadIdx.x & 31;
    const uint2* __restrict__ hp = (const uint2*)h;   // 4 halves per lane
    float di = g_dinv[node];
    uint2 sv = hp[(size_t)node * 32 + lane];          // self (already dinv-scaled)
    float2 a01 = __half22float2(*(__half2*)&sv.x);
    float2 a23 = __half22float2(*(__half2*)&sv.y);
    float4 acc = make_float4(a01.x, a01.y, a23.x, a23.y);
    int e0 = g_off[node] + g_boff[node >> 10];
    int e1 = g_off[node + 1] + g_boff[(node + 1) >> 10];
    for (int base = e0; base < e1; base += 32) {
        int t = base + lane;
        int idx = (t < e1) ? g_ssrc[t] : 0;           // one coalesced LDG per 32 edges
        int cnt = min(32, e1 - base);
        int j = 0;
        for (; j + 8 <= cnt; j += 8) {
            int s0 = __shfl_sync(0xFFFFFFFFu, idx, j);
            int s1 = __shfl_sync(0xFFFFFFFFu, idx, j + 1);
            int s2 = __shfl_sync(0xFFFFFFFFu, idx, j + 2);
            int s3 = __shfl_sync(0xFFFFFFFFu, idx, j + 3);
            int s4 = __shfl_sync(0xFFFFFFFFu, idx, j + 4);
            int s5 = __shfl_sync(0xFFFFFFFFu, idx, j + 5);
            int s6 = __shfl_sync(0xFFFFFFFFu, idx, j + 6);
            int s7 = __shfl_sync(0xFFFFFFFFu, idx, j + 7);
            uint2 v0 = hp[(size_t)s0 * 32 + lane];
            uint2 v1 = hp[(size_t)s1 * 32 + lane];
            uint2 v2 = hp[(size_t)s2 * 32 + lane];
            uint2 v3 = hp[(size_t)s3 * 32 + lane];
            uint2 v4 = hp[(size_t)s4 * 32 + lane];
            uint2 v5 = hp[(size_t)s5 * 32 + lane];
            uint2 v6 = hp[(size_t)s6 * 32 + lane];
            uint2 v7 = hp[(size_t)s7 * 32 + lane];
            float2 f;
            f = __half22float2(*(__half2*)&v0.x); acc.x += f.x; acc.y += f.y;
            f = __half22float2(*(__half2*)&v0.y); acc.z += f.x; acc.w += f.y;
            f = __half22float2(*(__half2*)&v1.x); acc.x += f.x; acc.y += f.y;
            f = __half22float2(*(__half2*)&v1.y); acc.z += f.x; acc.w += f.y;
            f = __half22float2(*(__half2*)&v2.x); acc.x += f.x; acc.y += f.y;
            f = __half22float2(*(__half2*)&v2.y); acc.z += f.x; acc.w += f.y;
            f = __half22float2(*(__half2*)&v3.x); acc.x += f.x; acc.y += f.y;
            f = __half22float2(*(__half2*)&v3.y); acc.z += f.x; acc.w += f.y;
            f = __half22float2(*(__half2*)&v4.x); acc.x += f.x; acc.y += f.y;
            f = __half22float2(*(__half2*)&v4.y); acc.z += f.x; acc.w += f.y;
            f = __half22float2(*(__half2*)&v5.x); acc.x += f.x; acc.y += f.y;
            f = __half22float2(*(__half2*)&v5.y); acc.z += f.x; acc.w += f.y;
            f = __half22float2(*(__half2*)&v6.x); acc.x += f.x; acc.y += f.y;
            f = __half22float2(*(__half2*)&v6.y); acc.z += f.x; acc.w += f.y;
            f = __half22float2(*(__half2*)&v7.x); acc.x += f.x; acc.y += f.y;
            f = __half22float2(*(__half2*)&v7.y); acc.z += f.x; acc.w += f.y;
        }
        for (; j < cnt; j++) {
            int s = __shfl_sync(0xFFFFFFFFu, idx, j);
            uint2 v = hp[(size_t)s * 32 + lane];
            float2 f;
            f = __half22float2(*(__half2*)&v.x); acc.x += f.x; acc.y += f.y;
            f = __half22float2(*(__half2*)&v.y); acc.z += f.x; acc.w += f.y;
        }
    }
    acc.x *= di; acc.y *= di; acc.z *= di; acc.w *= di;
    __half2 o01 = __floats2half2_rn(acc.x, acc.y);
    __half2 o23 = __floats2half2_rn(acc.z, acc.w);
    ((uint2*)agg)[(size_t)node * 32 + lane] = make_uint2(*(uint32_t*)&o01, *(uint32_t*)&o23);

    // fused BN statistics: block reduction over the 8 nodes, atomic into buckets
    rs[q][lane * 4 + 0] = acc.x; rs[q][lane * 4 + 1] = acc.y;
    rs[q][lane * 4 + 2] = acc.z; rs[q][lane * 4 + 3] = acc.w;
    rss[q][lane * 4 + 0] = acc.x * acc.x; rss[q][lane * 4 + 1] = acc.y * acc.y;
    rss[q][lane * 4 + 2] = acc.z * acc.z; rss[q][lane * 4 + 3] = acc.w * acc.w;
    __syncthreads();
    int tid = threadIdx.x;
    if (tid < DD) {
        float s = 0.f, ss = 0.f;
        #pragma unroll
        for (int k = 0; k < 8; k++) {
            s += rs[k][tid];
            ss += rss[k][tid];
        }
        int bucket = blockIdx.x & 7;
        atomicAdd(&g_stats[2 * layer + 0][bucket][tid], s);
        atomicAdd(&g_stats[2 * layer + 1][bucket][tid], ss);
    }
}

// ---------------- final: BN2 (from fused stats) + residual + leakyrelu ----------
__global__ __launch_bounds__(256) void k_final(const __half* __restrict__ agg,
                                               const float* __restrict__ x,
                                               float* __restrict__ out,
                                               const float* __restrict__ gamma,
                                               const float* __restrict__ beta) {
    __shared__ float sSc[DD];
    __shared__ float sSh[DD];
    int tid = threadIdx.x;
    if (tid < DD) {
        float s = 0.f, ss = 0.f;
        #pragma unroll
        for (int b = 0; b < 8; b++) {
            s += g_stats[2][b][tid];
            ss += g_stats[3][b][tid];
        }
        float mean = s * (1.0f / NN);
        float var = ss * (1.0f / NN) - mean * mean;
        float r = rsqrtf(var + EPSV);
        float sc = r * gamma[tid];
        sSc[tid] = sc;
        sSh[tid] = fmaf(-mean, sc, beta[tid]);
    }
    __syncthreads();
    int i = blockIdx.x * blockDim.x + tid;
    if (i >= NN * DD / 4) return;
    int c = (i & 31) * 4;
    uint2 u = ((const uint2*)agg)[i];
    float2 v01 = __half22float2(*(__half2*)&u.x);
    float2 v23 = __half22float2(*(__half2*)&u.y);
    float4 xr = ((const float4*)x)[i];
    float4 o;
    float y;
    y = fmaf(v01.x, sSc[c + 0], sSh[c + 0]) + xr.x; o.x = y > 0.f ? y : NEG * y;
    y = fmaf(v01.y, sSc[c + 1], sSh[c + 1]) + xr.y; o.y = y > 0.f ? y : NEG * y;
    y = fmaf(v23.x, sSc[c + 2], sSh[c + 2]) + xr.z; o.z = y > 0.f ? y : NEG * y;
    y = fmaf(v23.y, sSc[c + 3], sSh[c + 3]) + xr.w; o.w = y > 0.f ? y : NEG * y;
    ((float4*)out)[i] = o;
}

// ---------------- launch ----------------
extern "C" void kernel_launch(void* const* d_in, const int* in_sizes, int n_in,
                              void* d_out, int out_size) {
    const float* x   = (const float*)d_in[0];
    const int*   ei  = (const int*)d_in[1];
    const int*   src = ei;
    const int*   dst = ei + EE;
    const float* W1  = (const float*)d_in[2];
    // b1 = d_in[3]: cancels inside BatchNorm
    const float* g1  = (const float*)d_in[4];
    const float* be1 = (const float*)d_in[5];
    const float* W2  = (const float*)d_in[6];
    // b2 = d_in[7]: cancels likewise
    const float* g2  = (const float*)d_in[8];
    const float* be2 = (const float*)d_in[9];
    float* out = (float*)d_out;

    __half* p_h = nullptr;
    __half* p_buf = nullptr;
    int* p_cnt = nullptr;
    float* p_stats = nullptr;
    int* p_ctr = nullptr;
    uint2 *p_w1hi, *p_w1lo, *p_w2hi, *p_w2lo;
    cudaGetSymbolAddress((void**)&p_h, g_h);
    cudaGetSymbolAddress((void**)&p_buf, g_buf);
    cudaGetSymbolAddress((void**)&p_cnt, g_cnt);
    cudaGetSymbolAddress((void**)&p_stats, g_stats);
    cudaGetSymbolAddress((void**)&p_ctr, g_ctr);
    cudaGetSymbolAddress((void**)&p_w1hi, g_w1hi);
    cudaGetSymbolAddress((void**)&p_w1lo, g_w1lo);
    cudaGetSymbolAddress((void**)&p_w2hi, g_w2hi);
    cudaGetSymbolAddress((void**)&p_w2lo, g_w2lo);

    cudaFuncSetAttribute(k_gemm_l1, cudaFuncAttributeMaxDynamicSharedMemorySize, SMEMG);
    cudaFuncSetAttribute(k_gemm_l2, cudaFuncAttributeMaxDynamicSharedMemorySize, SMEMG);

    // second stream + events for fork-join (host-side; fall back if creation fails)
    cudaStream_t s2 = 0;
    bool forked = (cudaStreamCreateWithFlags(&s2, cudaStreamNonBlocking) == cudaSuccess);
    cudaEvent_t eFork = 0, eDinv = 0, eGemm = 0;
    if (forked) forked = (cudaEventCreateWithFlags(&eFork, cudaEventDisableTiming) == cudaSuccess);
    if (forked) forked = (cudaEventCreateWithFlags(&eDinv, cudaEventDisableTiming) == cudaSuccess);
    if (forked) forked = (cudaEventCreateWithFlags(&eGemm, cudaEventDisableTiming) == cudaSuccess);
    cudaStream_t sG = forked ? s2 : (cudaStream_t)0;

    // default stream: edge preprocessing. s2: weight prep + GEMM1 (needs dinv).
    cudaMemsetAsync(p_cnt, 0, NN * sizeof(int), 0);
    cudaMemsetAsync(p_stats, 0, sizeof(float) * 4 * 8 * DD, 0);
    cudaMemsetAsync(p_ctr, 0, sizeof(int), 0);
    if (forked) {
        cudaEventRecord(eFork, 0);
        cudaStreamWaitEvent(s2, eFork, 0);
    }
    k_prepw<<<32, 256, 0, sG>>>(W1, W2);
    k_hist<<<(EE / 4 + 255) / 256, 256>>>(dst);
    k_scan1<<<SCAN_BLK, 1024>>>();
    if (forked) {
        cudaEventRecord(eDinv, 0);
        cudaStreamWaitEvent(s2, eDinv, 0);
    }
    k_scatter<<<2048, 256>>>(src, dst);
    k_gemm_l1<<<(NN + 127) / 128, 256, SMEMG, sG>>>(x, p_w1hi, p_w1lo, p_h);
    if (forked) {
        cudaEventRecord(eGemm, s2);
        cudaStreamWaitEvent(0, eGemm, 0);   // join: agg needs scatter AND gemm1
    }

    // layer 1: aggregation with fused BN stats
    k_agg<<<NN / 8, 256>>>(p_h, p_buf, 0);

    // layer 2: GEMM (BN1 from stats + act fused), agg (fused stats), final
    k_gemm_l2<<<(NN + 127) / 128, 256, SMEMG>>>(p_buf, p_w2hi, p_w2lo, p_h, g1, be1);
    k_agg<<<NN / 8, 256>>>(p_h, p_buf, 1);
    k_final<<<(NN * DD / 4 + 255) / 256, 256>>>(p_buf, x, out, g2, be2);
}